// round 2
// baseline (speedup 1.0000x reference)
#include <cuda_runtime.h>
#include <cuda_bf16.h>

#define BATCH   4
#define TSEQ    4096
#define CDIM    512
#define HDIM    64
#define BT_TOTAL (BATCH * TSEQ)   // 16384

// Scratch for projected Q (pre-scaled by 8), K, V. 4 MB each — static device
// arrays per the allocation rules.
__device__ float g_q[BT_TOTAL * HDIM];
__device__ float g_k[BT_TOTAL * HDIM];
__device__ float g_v[BT_TOTAL * HDIM];

// ---------------------------------------------------------------------------
// Projection GEMM: out[16384,64] = x[16384,512] @ W[512,64]  (x3 matrices)
// grid (BT/128, 3), block 256. BM=128, BN=64, BK=32, per-thread 8x4 microtile.
// Q output fused-scaled by sqrt(HDIM)=8 (reference MULTIPLIES by the scale).
// ---------------------------------------------------------------------------
__global__ __launch_bounds__(256) void proj_kernel(
    const float* __restrict__ x,
    const float* __restrict__ Wq,
    const float* __restrict__ Wk,
    const float* __restrict__ Wv)
{
    const int mat = blockIdx.y;
    const float* __restrict__ W = (mat == 0) ? Wq : (mat == 1) ? Wk : Wv;
    float* __restrict__ out     = (mat == 0) ? g_q : (mat == 1) ? g_k : g_v;
    const int row0 = blockIdx.x * 128;

    __shared__ float As[32][132];   // [BK][BM+pad], A stored transposed
    __shared__ float Bs[32][64];    // [BK][BN]

    const int tid = threadIdx.x;
    const int tm = (tid / 16) * 8;  // 0..120
    const int tn = (tid % 16) * 4;  // 0..60

    float acc[8][4] = {};

    for (int k0 = 0; k0 < CDIM; k0 += 32) {
        // Load A tile 128x32 (transposed into As). 8 float4-quads per row.
        {
            const int tr = tid / 8;            // 0..31
            const int tc = (tid % 8) * 4;      // 0..28
            #pragma unroll
            for (int p = 0; p < 4; p++) {
                const int r = tr + p * 32;
                float4 va = *reinterpret_cast<const float4*>(
                    &x[(long)(row0 + r) * CDIM + k0 + tc]);
                As[tc + 0][r] = va.x;
                As[tc + 1][r] = va.y;
                As[tc + 2][r] = va.z;
                As[tc + 3][r] = va.w;
            }
        }
        // Load B tile 32x64.
        {
            const int tr = tid / 16;           // 0..15
            const int tc = (tid % 16) * 4;     // 0..60
            #pragma unroll
            for (int p = 0; p < 2; p++) {
                const int r = tr + p * 16;
                *reinterpret_cast<float4*>(&Bs[r][tc]) =
                    *reinterpret_cast<const float4*>(&W[(long)(k0 + r) * HDIM + tc]);
            }
        }
        __syncthreads();

        #pragma unroll
        for (int kk = 0; kk < 32; kk++) {
            float a[8], b[4];
            #pragma unroll
            for (int i = 0; i < 8; i++) a[i] = As[kk][tm + i];
            #pragma unroll
            for (int j = 0; j < 4; j++) b[j] = Bs[kk][tn + j];
            #pragma unroll
            for (int i = 0; i < 8; i++)
                #pragma unroll
                for (int j = 0; j < 4; j++)
                    acc[i][j] += a[i] * b[j];
        }
        __syncthreads();
    }

    const float scale = (mat == 0) ? 8.0f : 1.0f;  // sqrt(64), multiplied as in ref
    #pragma unroll
    for (int i = 0; i < 8; i++)
        #pragma unroll
        for (int j = 0; j < 4; j++)
            out[(long)(row0 + tm + i) * HDIM + tn + j] = acc[i][j] * scale;
}

// ---------------------------------------------------------------------------
// Flash attention (no mask): grid (TSEQ/128, BATCH), block 128.
// One query row per thread: q[64] + acc[64] in registers, online softmax,
// K/V streamed through smem in 32-key tiles, float4 broadcast smem reads.
// ---------------------------------------------------------------------------
__global__ __launch_bounds__(128) void attn_kernel(float* __restrict__ out)
{
    const int b = blockIdx.y;
    const int r = blockIdx.x * 128 + threadIdx.x;

    float qr[HDIM];
    {
        const float* __restrict__ qrow = &g_q[((long)b * TSEQ + r) * HDIM];
        #pragma unroll
        for (int c = 0; c < HDIM; c += 4) {
            float4 t = *reinterpret_cast<const float4*>(&qrow[c]);
            qr[c] = t.x; qr[c + 1] = t.y; qr[c + 2] = t.z; qr[c + 3] = t.w;
        }
    }

    float acc[HDIM] = {};
    float m = -1e30f, l = 0.0f;

    __shared__ float Ks[32][64];
    __shared__ float Vs[32][64];

    const float* __restrict__ kb = &g_k[(long)b * TSEQ * HDIM];
    const float* __restrict__ vb = &g_v[(long)b * TSEQ * HDIM];

    for (int t0 = 0; t0 < TSEQ; t0 += 32) {
        __syncthreads();
        {
            const int tid = threadIdx.x;
            const int jr = tid / 16;            // 0..7
            const int jc = (tid % 16) * 4;      // 0..60
            #pragma unroll
            for (int p = 0; p < 4; p++) {
                const int j = jr + p * 8;
                *reinterpret_cast<float4*>(&Ks[j][jc]) =
                    *reinterpret_cast<const float4*>(&kb[(long)(t0 + j) * HDIM + jc]);
                *reinterpret_cast<float4*>(&Vs[j][jc]) =
                    *reinterpret_cast<const float4*>(&vb[(long)(t0 + j) * HDIM + jc]);
            }
        }
        __syncthreads();

        // scores for 32 keys
        float s[32];
        float tmax = -1e30f;
        #pragma unroll 4
        for (int j = 0; j < 32; j++) {
            const float4* kj = reinterpret_cast<const float4*>(Ks[j]);
            float4 a4 = make_float4(0.f, 0.f, 0.f, 0.f);
            #pragma unroll
            for (int c4 = 0; c4 < 16; c4++) {
                float4 kv = kj[c4];
                a4.x += qr[4 * c4 + 0] * kv.x;
                a4.y += qr[4 * c4 + 1] * kv.y;
                a4.z += qr[4 * c4 + 2] * kv.z;
                a4.w += qr[4 * c4 + 3] * kv.w;
            }
            const float sj = (a4.x + a4.y) + (a4.z + a4.w);
            s[j] = sj;
            tmax = fmaxf(tmax, sj);
        }

        const float nm = fmaxf(m, tmax);
        const float alpha = __expf(m - nm);   // exp(-huge) -> 0 on first tile
        m = nm;
        l *= alpha;
        #pragma unroll
        for (int h = 0; h < HDIM; h++) acc[h] *= alpha;

        #pragma unroll 2
        for (int j = 0; j < 32; j++) {
            const float p = __expf(s[j] - nm);
            l += p;
            const float4* vj = reinterpret_cast<const float4*>(Vs[j]);
            #pragma unroll
            for (int h4 = 0; h4 < 16; h4++) {
                float4 vv = vj[h4];
                acc[4 * h4 + 0] += p * vv.x;
                acc[4 * h4 + 1] += p * vv.y;
                acc[4 * h4 + 2] += p * vv.z;
                acc[4 * h4 + 3] += p * vv.w;
            }
        }
    }

    const float inv = 1.0f / l;
    float* __restrict__ orow = &out[((long)b * TSEQ + r) * HDIM];
    #pragma unroll
    for (int h = 0; h < HDIM; h += 4) {
        float4 t;
        t.x = acc[h + 0] * inv;
        t.y = acc[h + 1] * inv;
        t.z = acc[h + 2] * inv;
        t.w = acc[h + 3] * inv;
        *reinterpret_cast<float4*>(&orow[h]) = t;
    }
}

// ---------------------------------------------------------------------------
extern "C" void kernel_launch(void* const* d_in, const int* in_sizes, int n_in,
                              void* d_out, int out_size)
{
    const float* x  = (const float*)d_in[0];
    const float* Wq = (const float*)d_in[1];
    const float* Wk = (const float*)d_in[2];
    const float* Wv = (const float*)d_in[3];
    float* out = (float*)d_out;

    dim3 pg(BT_TOTAL / 128, 3);
    proj_kernel<<<pg, 256>>>(x, Wq, Wk, Wv);

    dim3 ag(TSEQ / 128, BATCH);
    attn_kernel<<<ag, 128>>>(out);
}

// round 3
// speedup vs baseline: 1.0475x; 1.0475x over previous
#include <cuda_runtime.h>
#include <cuda_bf16.h>

#define BATCH   4
#define TSEQ    4096
#define CDIM    512
#define HDIM    64
#define BT_TOTAL (BATCH * TSEQ)   // 16384
#define NSPLIT  4
#define KEYS_PER_SPLIT (TSEQ / NSPLIT)   // 1024
#define ROWS_PER_CTA 64

// Scratch (static device arrays per allocation rules).
__device__ float g_q[BT_TOTAL * HDIM];
__device__ float g_k[BT_TOTAL * HDIM];
__device__ float g_v[BT_TOTAL * HDIM];
// split-KV partials
__device__ float g_pacc[NSPLIT][BT_TOTAL][HDIM];   // 16 MB
__device__ float g_pm[NSPLIT][BT_TOTAL];
__device__ float g_pl[NSPLIT][BT_TOTAL];

// ---------------------------------------------------------------------------
// Projection GEMM: out[16384,64] = x[16384,512] @ W[512,64]  (x3 matrices)
// Q output fused-scaled by sqrt(HDIM)=8 (reference MULTIPLIES by the scale).
// ---------------------------------------------------------------------------
__global__ __launch_bounds__(256) void proj_kernel(
    const float* __restrict__ x,
    const float* __restrict__ Wq,
    const float* __restrict__ Wk,
    const float* __restrict__ Wv)
{
    const int mat = blockIdx.y;
    const float* __restrict__ W = (mat == 0) ? Wq : (mat == 1) ? Wk : Wv;
    float* __restrict__ out     = (mat == 0) ? g_q : (mat == 1) ? g_k : g_v;
    const int row0 = blockIdx.x * 128;

    __shared__ float As[32][132];
    __shared__ float Bs[32][64];

    const int tid = threadIdx.x;
    const int tm = (tid / 16) * 8;
    const int tn = (tid % 16) * 4;

    float acc[8][4] = {};

    for (int k0 = 0; k0 < CDIM; k0 += 32) {
        {
            const int tr = tid / 8;
            const int tc = (tid % 8) * 4;
            #pragma unroll
            for (int p = 0; p < 4; p++) {
                const int r = tr + p * 32;
                float4 va = *reinterpret_cast<const float4*>(
                    &x[(long)(row0 + r) * CDIM + k0 + tc]);
                As[tc + 0][r] = va.x;
                As[tc + 1][r] = va.y;
                As[tc + 2][r] = va.z;
                As[tc + 3][r] = va.w;
            }
        }
        {
            const int tr = tid / 16;
            const int tc = (tid % 16) * 4;
            #pragma unroll
            for (int p = 0; p < 2; p++) {
                const int r = tr + p * 16;
                *reinterpret_cast<float4*>(&Bs[r][tc]) =
                    *reinterpret_cast<const float4*>(&W[(long)(k0 + r) * HDIM + tc]);
            }
        }
        __syncthreads();

        #pragma unroll
        for (int kk = 0; kk < 32; kk++) {
            float a[8], b[4];
            #pragma unroll
            for (int i = 0; i < 8; i++) a[i] = As[kk][tm + i];
            #pragma unroll
            for (int j = 0; j < 4; j++) b[j] = Bs[kk][tn + j];
            #pragma unroll
            for (int i = 0; i < 8; i++)
                #pragma unroll
                for (int j = 0; j < 4; j++)
                    acc[i][j] += a[i] * b[j];
        }
        __syncthreads();
    }

    const float scale = (mat == 0) ? 8.0f : 1.0f;
    #pragma unroll
    for (int i = 0; i < 8; i++)
        #pragma unroll
        for (int j = 0; j < 4; j++)
            out[(long)(row0 + tm + i) * HDIM + tn + j] = acc[i][j] * scale;
}

// ---------------------------------------------------------------------------
// Flash attention partial, split-KV. grid (TSEQ/64, BATCH, NSPLIT), block 64.
// One query row per thread; each CTA covers KEYS_PER_SPLIT keys. Writes
// unnormalized (m, l, acc) partials.
// ---------------------------------------------------------------------------
__global__ __launch_bounds__(64, 5) void attn_partial_kernel()
{
    const int b     = blockIdx.y;
    const int split = blockIdx.z;
    const int r     = blockIdx.x * ROWS_PER_CTA + threadIdx.x;
    const long row  = (long)b * TSEQ + r;

    float qr[HDIM];
    {
        const float* __restrict__ qrow = &g_q[row * HDIM];
        #pragma unroll
        for (int c = 0; c < HDIM; c += 4) {
            float4 t = *reinterpret_cast<const float4*>(&qrow[c]);
            qr[c] = t.x; qr[c + 1] = t.y; qr[c + 2] = t.z; qr[c + 3] = t.w;
        }
    }

    float acc[HDIM] = {};
    float m = -1e30f, l = 0.0f;

    __shared__ float Ks[32][64];
    __shared__ float Vs[32][64];

    const int tbase = split * KEYS_PER_SPLIT;
    const float* __restrict__ kb = &g_k[(long)b * TSEQ * HDIM];
    const float* __restrict__ vb = &g_v[(long)b * TSEQ * HDIM];

    for (int t0 = tbase; t0 < tbase + KEYS_PER_SPLIT; t0 += 32) {
        __syncthreads();
        {
            const int tid = threadIdx.x;
            const int jr = tid / 16;            // 0..3
            const int jc = (tid % 16) * 4;      // 0..60
            #pragma unroll
            for (int p = 0; p < 8; p++) {
                const int j = jr + p * 4;
                *reinterpret_cast<float4*>(&Ks[j][jc]) =
                    *reinterpret_cast<const float4*>(&kb[(long)(t0 + j) * HDIM + jc]);
                *reinterpret_cast<float4*>(&Vs[j][jc]) =
                    *reinterpret_cast<const float4*>(&vb[(long)(t0 + j) * HDIM + jc]);
            }
        }
        __syncthreads();

        float s[32];
        float tmax = -1e30f;
        #pragma unroll 4
        for (int j = 0; j < 32; j++) {
            const float4* kj = reinterpret_cast<const float4*>(Ks[j]);
            float4 a4 = make_float4(0.f, 0.f, 0.f, 0.f);
            #pragma unroll
            for (int c4 = 0; c4 < 16; c4++) {
                float4 kv = kj[c4];
                a4.x += qr[4 * c4 + 0] * kv.x;
                a4.y += qr[4 * c4 + 1] * kv.y;
                a4.z += qr[4 * c4 + 2] * kv.z;
                a4.w += qr[4 * c4 + 3] * kv.w;
            }
            const float sj = (a4.x + a4.y) + (a4.z + a4.w);
            s[j] = sj;
            tmax = fmaxf(tmax, sj);
        }

        const float nm = fmaxf(m, tmax);
        const float alpha = __expf(m - nm);
        m = nm;
        l *= alpha;
        #pragma unroll
        for (int h = 0; h < HDIM; h++) acc[h] *= alpha;

        #pragma unroll 2
        for (int j = 0; j < 32; j++) {
            const float p = __expf(s[j] - nm);
            l += p;
            const float4* vj = reinterpret_cast<const float4*>(Vs[j]);
            #pragma unroll
            for (int h4 = 0; h4 < 16; h4++) {
                float4 vv = vj[h4];
                acc[4 * h4 + 0] += p * vv.x;
                acc[4 * h4 + 1] += p * vv.y;
                acc[4 * h4 + 2] += p * vv.z;
                acc[4 * h4 + 3] += p * vv.w;
            }
        }
    }

    g_pm[split][row] = m;
    g_pl[split][row] = l;
    float* __restrict__ prow = g_pacc[split][row];
    #pragma unroll
    for (int h = 0; h < HDIM; h += 4) {
        float4 t;
        t.x = acc[h + 0]; t.y = acc[h + 1]; t.z = acc[h + 2]; t.w = acc[h + 3];
        *reinterpret_cast<float4*>(&prow[h]) = t;
    }
}

// ---------------------------------------------------------------------------
// Combine split-KV partials: out = sum_i w_i*acc_i / sum_i w_i*l_i,
// w_i = exp(m_i - M), M = max_i m_i. One row per thread.
// ---------------------------------------------------------------------------
__global__ __launch_bounds__(128) void combine_kernel(float* __restrict__ out)
{
    const long row = (long)blockIdx.x * 128 + threadIdx.x;

    float m[NSPLIT], w[NSPLIT];
    float M = -1e30f;
    #pragma unroll
    for (int i = 0; i < NSPLIT; i++) {
        m[i] = g_pm[i][row];
        M = fmaxf(M, m[i]);
    }
    float L = 0.0f;
    #pragma unroll
    for (int i = 0; i < NSPLIT; i++) {
        w[i] = __expf(m[i] - M);
        L += w[i] * g_pl[i][row];
    }
    const float inv = 1.0f / L;

    float* __restrict__ orow = &out[row * HDIM];
    #pragma unroll
    for (int h = 0; h < HDIM; h += 4) {
        float4 a = make_float4(0.f, 0.f, 0.f, 0.f);
        #pragma unroll
        for (int i = 0; i < NSPLIT; i++) {
            float4 p = *reinterpret_cast<const float4*>(&g_pacc[i][row][h]);
            a.x += w[i] * p.x;
            a.y += w[i] * p.y;
            a.z += w[i] * p.z;
            a.w += w[i] * p.w;
        }
        a.x *= inv; a.y *= inv; a.z *= inv; a.w *= inv;
        *reinterpret_cast<float4*>(&orow[h]) = a;
    }
}

// ---------------------------------------------------------------------------
extern "C" void kernel_launch(void* const* d_in, const int* in_sizes, int n_in,
                              void* d_out, int out_size)
{
    const float* x  = (const float*)d_in[0];
    const float* Wq = (const float*)d_in[1];
    const float* Wk = (const float*)d_in[2];
    const float* Wv = (const float*)d_in[3];
    float* out = (float*)d_out;

    dim3 pg(BT_TOTAL / 128, 3);
    proj_kernel<<<pg, 256>>>(x, Wq, Wk, Wv);

    dim3 ag(TSEQ / ROWS_PER_CTA, BATCH, NSPLIT);
    attn_partial_kernel<<<ag, ROWS_PER_CTA>>>();

    combine_kernel<<<BT_TOTAL / 128, 128>>>(out);
}

// round 4
// speedup vs baseline: 1.0645x; 1.0162x over previous
#include <cuda_runtime.h>
#include <cuda_bf16.h>

#define BATCH   4
#define TSEQ    4096
#define CDIM    512
#define HDIM    64
#define BT_TOTAL (BATCH * TSEQ)   // 16384
#define NSPLIT  4
#define KEYS_PER_SPLIT (TSEQ / NSPLIT)   // 1024
#define ROWS_PER_CTA 64

typedef unsigned long long u64;

// ---- packed fp32x2 helpers (Blackwell dual-pumped fp32 path) ----
__device__ __forceinline__ u64 ffma2(u64 a, u64 b, u64 c) {
    u64 d;
    asm("fma.rn.f32x2 %0, %1, %2, %3;" : "=l"(d) : "l"(a), "l"(b), "l"(c));
    return d;
}
__device__ __forceinline__ u64 fmul2(u64 a, u64 b) {
    u64 d;
    asm("mul.rn.f32x2 %0, %1, %2;" : "=l"(d) : "l"(a), "l"(b));
    return d;
}
__device__ __forceinline__ u64 bcast2(float x) {
    u64 d;
    asm("mov.b64 %0, {%1, %1};" : "=l"(d) : "f"(x));
    return d;
}
__device__ __forceinline__ void unpack2(u64 v, float& lo, float& hi) {
    asm("mov.b64 {%0, %1}, %2;" : "=f"(lo), "=f"(hi) : "l"(v));
}

// Scratch (static device arrays per allocation rules).
__device__ float g_q[BT_TOTAL * HDIM];
__device__ float g_k[BT_TOTAL * HDIM];
__device__ float g_v[BT_TOTAL * HDIM];
// split-KV partials
__device__ float g_pacc[NSPLIT][BT_TOTAL][HDIM];   // 16 MB
__device__ float g_pm[NSPLIT][BT_TOTAL];
__device__ float g_pl[NSPLIT][BT_TOTAL];

// ---------------------------------------------------------------------------
// Projection GEMM: out[16384,64] = x[16384,512] @ W[512,64]  (x3 matrices)
// Q output fused-scaled by sqrt(HDIM)=8 (reference MULTIPLIES by the scale).
// Microkernel uses fma.rn.f32x2: M-pairs loaded packed from As, B broadcast.
// ---------------------------------------------------------------------------
__global__ __launch_bounds__(256) void proj_kernel(
    const float* __restrict__ x,
    const float* __restrict__ Wq,
    const float* __restrict__ Wk,
    const float* __restrict__ Wv)
{
    const int mat = blockIdx.y;
    const float* __restrict__ W = (mat == 0) ? Wq : (mat == 1) ? Wk : Wv;
    float* __restrict__ out     = (mat == 0) ? g_q : (mat == 1) ? g_k : g_v;
    const int row0 = blockIdx.x * 128;

    __shared__ float As[32][132];   // 132*4 = 528 bytes/row (16B multiple)
    __shared__ float Bs[32][64];

    const int tid = threadIdx.x;
    const int tm = (tid / 16) * 8;
    const int tn = (tid % 16) * 4;

    u64 acc2[4][4];                  // [m-pair][n]
    #pragma unroll
    for (int i = 0; i < 4; i++)
        #pragma unroll
        for (int j = 0; j < 4; j++) acc2[i][j] = 0ull;

    for (int k0 = 0; k0 < CDIM; k0 += 32) {
        {
            const int tr = tid / 8;
            const int tc = (tid % 8) * 4;
            #pragma unroll
            for (int p = 0; p < 4; p++) {
                const int r = tr + p * 32;
                float4 va = *reinterpret_cast<const float4*>(
                    &x[(long)(row0 + r) * CDIM + k0 + tc]);
                As[tc + 0][r] = va.x;
                As[tc + 1][r] = va.y;
                As[tc + 2][r] = va.z;
                As[tc + 3][r] = va.w;
            }
        }
        {
            const int tr = tid / 16;
            const int tc = (tid % 16) * 4;
            #pragma unroll
            for (int p = 0; p < 2; p++) {
                const int r = tr + p * 16;
                *reinterpret_cast<float4*>(&Bs[r][tc]) =
                    *reinterpret_cast<const float4*>(&W[(long)(k0 + r) * HDIM + tc]);
            }
        }
        __syncthreads();

        #pragma unroll
        for (int kk = 0; kk < 32; kk++) {
            // 8 M-values as 4 packed pairs (contiguous in As)
            const ulonglong2* arow =
                reinterpret_cast<const ulonglong2*>(&As[kk][tm]);
            ulonglong2 a01 = arow[0];
            ulonglong2 a23 = arow[1];
            u64 a2[4] = {a01.x, a01.y, a23.x, a23.y};
            // 4 N-values broadcast-packed
            float4 bv = *reinterpret_cast<const float4*>(&Bs[kk][tn]);
            u64 b2[4] = {bcast2(bv.x), bcast2(bv.y), bcast2(bv.z), bcast2(bv.w)};
            #pragma unroll
            for (int i = 0; i < 4; i++)
                #pragma unroll
                for (int j = 0; j < 4; j++)
                    acc2[i][j] = ffma2(a2[i], b2[j], acc2[i][j]);
        }
        __syncthreads();
    }

    const float scale = (mat == 0) ? 8.0f : 1.0f;
    #pragma unroll
    for (int i = 0; i < 4; i++) {
        float lo[4], hi[4];
        #pragma unroll
        for (int j = 0; j < 4; j++) unpack2(acc2[i][j], lo[j], hi[j]);
        float4 r0, r1;
        r0.x = lo[0] * scale; r0.y = lo[1] * scale; r0.z = lo[2] * scale; r0.w = lo[3] * scale;
        r1.x = hi[0] * scale; r1.y = hi[1] * scale; r1.z = hi[2] * scale; r1.w = hi[3] * scale;
        *reinterpret_cast<float4*>(&out[(long)(row0 + tm + 2 * i + 0) * HDIM + tn]) = r0;
        *reinterpret_cast<float4*>(&out[(long)(row0 + tm + 2 * i + 1) * HDIM + tn]) = r1;
    }
}

// ---------------------------------------------------------------------------
// Flash attention partial, split-KV. grid (TSEQ/64, BATCH, NSPLIT), block 64.
// One query row per thread. All dot products / accumulations via fma.rn.f32x2.
// ---------------------------------------------------------------------------
__global__ __launch_bounds__(64, 5) void attn_partial_kernel()
{
    const int b     = blockIdx.y;
    const int split = blockIdx.z;
    const int r     = blockIdx.x * ROWS_PER_CTA + threadIdx.x;
    const long row  = (long)b * TSEQ + r;

    // q row: 32 packed pairs
    u64 qr2[32];
    {
        const ulonglong2* qrow =
            reinterpret_cast<const ulonglong2*>(&g_q[row * HDIM]);
        #pragma unroll
        for (int i = 0; i < 16; i++) {
            ulonglong2 t = qrow[i];
            qr2[2 * i] = t.x;
            qr2[2 * i + 1] = t.y;
        }
    }

    u64 acc2[32];
    #pragma unroll
    for (int i = 0; i < 32; i++) acc2[i] = 0ull;
    float m = -1e30f, l = 0.0f;

    __shared__ float Ks[32][64];
    __shared__ float Vs[32][64];

    const int tbase = split * KEYS_PER_SPLIT;
    const float* __restrict__ kb = &g_k[(long)b * TSEQ * HDIM];
    const float* __restrict__ vb = &g_v[(long)b * TSEQ * HDIM];

    for (int t0 = tbase; t0 < tbase + KEYS_PER_SPLIT; t0 += 32) {
        __syncthreads();
        {
            const int tid = threadIdx.x;
            const int jr = tid / 16;            // 0..3
            const int jc = (tid % 16) * 4;      // 0..60
            #pragma unroll
            for (int p = 0; p < 8; p++) {
                const int j = jr + p * 4;
                *reinterpret_cast<float4*>(&Ks[j][jc]) =
                    *reinterpret_cast<const float4*>(&kb[(long)(t0 + j) * HDIM + jc]);
                *reinterpret_cast<float4*>(&Vs[j][jc]) =
                    *reinterpret_cast<const float4*>(&vb[(long)(t0 + j) * HDIM + jc]);
            }
        }
        __syncthreads();

        // scores for 32 keys via packed FMA
        float s[32];
        float tmax = -1e30f;
        #pragma unroll 4
        for (int j = 0; j < 32; j++) {
            const ulonglong2* kj = reinterpret_cast<const ulonglong2*>(Ks[j]);
            u64 aA = 0ull, aB = 0ull;
            #pragma unroll
            for (int c = 0; c < 16; c++) {
                ulonglong2 kp = kj[c];
                aA = ffma2(qr2[2 * c], kp.x, aA);
                aB = ffma2(qr2[2 * c + 1], kp.y, aB);
            }
            float ax, ay, az, aw;
            unpack2(aA, ax, ay);
            unpack2(aB, az, aw);
            const float sj = (ax + az) + (ay + aw);
            s[j] = sj;
            tmax = fmaxf(tmax, sj);
        }

        const float nm = fmaxf(m, tmax);
        const float alpha = __expf(m - nm);
        m = nm;
        l *= alpha;
        {
            const u64 al2 = bcast2(alpha);
            #pragma unroll
            for (int h = 0; h < 32; h++) acc2[h] = fmul2(acc2[h], al2);
        }

        #pragma unroll 2
        for (int j = 0; j < 32; j++) {
            const float p = __expf(s[j] - nm);
            l += p;
            const u64 p2 = bcast2(p);
            const ulonglong2* vj = reinterpret_cast<const ulonglong2*>(Vs[j]);
            #pragma unroll
            for (int h = 0; h < 16; h++) {
                ulonglong2 vv = vj[h];
                acc2[2 * h]     = ffma2(p2, vv.x, acc2[2 * h]);
                acc2[2 * h + 1] = ffma2(p2, vv.y, acc2[2 * h + 1]);
            }
        }
    }

    g_pm[split][row] = m;
    g_pl[split][row] = l;
    ulonglong2* prow = reinterpret_cast<ulonglong2*>(g_pacc[split][row]);
    #pragma unroll
    for (int h = 0; h < 16; h++) {
        ulonglong2 t;
        t.x = acc2[2 * h];
        t.y = acc2[2 * h + 1];
        prow[h] = t;
    }
}

// ---------------------------------------------------------------------------
// Combine split-KV partials: out = sum_i w_i*acc_i / sum_i w_i*l_i.
// ---------------------------------------------------------------------------
__global__ __launch_bounds__(128) void combine_kernel(float* __restrict__ out)
{
    const long row = (long)blockIdx.x * 128 + threadIdx.x;

    float m[NSPLIT], w[NSPLIT];
    float M = -1e30f;
    #pragma unroll
    for (int i = 0; i < NSPLIT; i++) {
        m[i] = g_pm[i][row];
        M = fmaxf(M, m[i]);
    }
    float L = 0.0f;
    #pragma unroll
    for (int i = 0; i < NSPLIT; i++) {
        w[i] = __expf(m[i] - M);
        L += w[i] * g_pl[i][row];
    }
    const float inv = 1.0f / L;

    float* __restrict__ orow = &out[row * HDIM];
    #pragma unroll
    for (int h = 0; h < HDIM; h += 4) {
        float4 a = make_float4(0.f, 0.f, 0.f, 0.f);
        #pragma unroll
        for (int i = 0; i < NSPLIT; i++) {
            float4 p = *reinterpret_cast<const float4*>(&g_pacc[i][row][h]);
            a.x += w[i] * p.x;
            a.y += w[i] * p.y;
            a.z += w[i] * p.z;
            a.w += w[i] * p.w;
        }
        a.x *= inv; a.y *= inv; a.z *= inv; a.w *= inv;
        *reinterpret_cast<float4*>(&orow[h]) = a;
    }
}

// ---------------------------------------------------------------------------
extern "C" void kernel_launch(void* const* d_in, const int* in_sizes, int n_in,
                              void* d_out, int out_size)
{
    const float* x  = (const float*)d_in[0];
    const float* Wq = (const float*)d_in[1];
    const float* Wk = (const float*)d_in[2];
    const float* Wv = (const float*)d_in[3];
    float* out = (float*)d_out;

    dim3 pg(BT_TOTAL / 128, 3);
    proj_kernel<<<pg, 256>>>(x, Wq, Wk, Wv);

    dim3 ag(TSEQ / ROWS_PER_CTA, BATCH, NSPLIT);
    attn_partial_kernel<<<ag, ROWS_PER_CTA>>>();

    combine_kernel<<<BT_TOTAL / 128, 128>>>(out);
}

// round 5
// speedup vs baseline: 1.4184x; 1.3325x over previous
#include <cuda_runtime.h>

#define BATCH   4
#define TSEQ    4096
#define CDIM    512
#define HDIM    64
#define BT_TOTAL (BATCH * TSEQ)   // 16384
#define QTILE   64
#define KTILE   64
#define PSTR    68                 // padded row stride (floats): 68*4=272B = 16B multiple

typedef unsigned long long u64;

// ---- packed fp32x2 helpers (used by proj kernel) ----
__device__ __forceinline__ u64 ffma2(u64 a, u64 b, u64 c) {
    u64 d;
    asm("fma.rn.f32x2 %0, %1, %2, %3;" : "=l"(d) : "l"(a), "l"(b), "l"(c));
    return d;
}
__device__ __forceinline__ u64 bcast2(float x) {
    u64 d;
    asm("mov.b64 %0, {%1, %1};" : "=l"(d) : "f"(x));
    return d;
}
__device__ __forceinline__ void unpack2(u64 v, float& lo, float& hi) {
    asm("mov.b64 {%0, %1}, %2;" : "=f"(lo), "=f"(hi) : "l"(v));
}

// ---- tf32 helpers ----
__device__ __forceinline__ float tf32_hi(float a) {
    unsigned u;
    asm("cvt.rna.tf32.f32 %0, %1;" : "=r"(u) : "f"(a));
    return __uint_as_float(u);
}
__device__ __forceinline__ void mma_tf32(
    float& c0, float& c1, float& c2, float& c3,
    float a0, float a1, float a2, float a3,
    float b0, float b1)
{
    unsigned A0 = __float_as_uint(a0), A1 = __float_as_uint(a1);
    unsigned A2 = __float_as_uint(a2), A3 = __float_as_uint(a3);
    unsigned B0 = __float_as_uint(b0), B1 = __float_as_uint(b1);
    asm("mma.sync.aligned.m16n8k8.row.col.f32.tf32.tf32.f32 "
        "{%0,%1,%2,%3},{%4,%5,%6,%7},{%8,%9},{%0,%1,%2,%3};"
        : "+f"(c0), "+f"(c1), "+f"(c2), "+f"(c3)
        : "r"(A0), "r"(A1), "r"(A2), "r"(A3), "r"(B0), "r"(B1));
}

// Scratch (static device arrays per allocation rules).
__device__ float g_q[BT_TOTAL * HDIM];
__device__ float g_k[BT_TOTAL * HDIM];
__device__ float g_v[BT_TOTAL * HDIM];

// ---------------------------------------------------------------------------
// Projection GEMM (unchanged from R3): out[16384,64] = x @ W, x3 matrices.
// Q fused-scaled by sqrt(HDIM)=8.
// ---------------------------------------------------------------------------
__global__ __launch_bounds__(256) void proj_kernel(
    const float* __restrict__ x,
    const float* __restrict__ Wq,
    const float* __restrict__ Wk,
    const float* __restrict__ Wv)
{
    const int mat = blockIdx.y;
    const float* __restrict__ W = (mat == 0) ? Wq : (mat == 1) ? Wk : Wv;
    float* __restrict__ out     = (mat == 0) ? g_q : (mat == 1) ? g_k : g_v;
    const int row0 = blockIdx.x * 128;

    __shared__ float As[32][132];
    __shared__ float Bs[32][64];

    const int tid = threadIdx.x;
    const int tm = (tid / 16) * 8;
    const int tn = (tid % 16) * 4;

    u64 acc2[4][4];
    #pragma unroll
    for (int i = 0; i < 4; i++)
        #pragma unroll
        for (int j = 0; j < 4; j++) acc2[i][j] = 0ull;

    for (int k0 = 0; k0 < CDIM; k0 += 32) {
        {
            const int tr = tid / 8;
            const int tc = (tid % 8) * 4;
            #pragma unroll
            for (int p = 0; p < 4; p++) {
                const int r = tr + p * 32;
                float4 va = *reinterpret_cast<const float4*>(
                    &x[(long)(row0 + r) * CDIM + k0 + tc]);
                As[tc + 0][r] = va.x;
                As[tc + 1][r] = va.y;
                As[tc + 2][r] = va.z;
                As[tc + 3][r] = va.w;
            }
        }
        {
            const int tr = tid / 16;
            const int tc = (tid % 16) * 4;
            #pragma unroll
            for (int p = 0; p < 2; p++) {
                const int r = tr + p * 16;
                *reinterpret_cast<float4*>(&Bs[r][tc]) =
                    *reinterpret_cast<const float4*>(&W[(long)(k0 + r) * HDIM + tc]);
            }
        }
        __syncthreads();

        #pragma unroll
        for (int kk = 0; kk < 32; kk++) {
            const ulonglong2* arow =
                reinterpret_cast<const ulonglong2*>(&As[kk][tm]);
            ulonglong2 a01 = arow[0];
            ulonglong2 a23 = arow[1];
            u64 a2[4] = {a01.x, a01.y, a23.x, a23.y};
            float4 bv = *reinterpret_cast<const float4*>(&Bs[kk][tn]);
            u64 b2[4] = {bcast2(bv.x), bcast2(bv.y), bcast2(bv.z), bcast2(bv.w)};
            #pragma unroll
            for (int i = 0; i < 4; i++)
                #pragma unroll
                for (int j = 0; j < 4; j++)
                    acc2[i][j] = ffma2(a2[i], b2[j], acc2[i][j]);
        }
        __syncthreads();
    }

    const float scale = (mat == 0) ? 8.0f : 1.0f;
    #pragma unroll
    for (int i = 0; i < 4; i++) {
        float lo[4], hi[4];
        #pragma unroll
        for (int j = 0; j < 4; j++) unpack2(acc2[i][j], lo[j], hi[j]);
        float4 r0, r1;
        r0.x = lo[0] * scale; r0.y = lo[1] * scale; r0.z = lo[2] * scale; r0.w = lo[3] * scale;
        r1.x = hi[0] * scale; r1.y = hi[1] * scale; r1.z = hi[2] * scale; r1.w = hi[3] * scale;
        *reinterpret_cast<float4*>(&out[(long)(row0 + tm + 2 * i + 0) * HDIM + tn]) = r0;
        *reinterpret_cast<float4*>(&out[(long)(row0 + tm + 2 * i + 1) * HDIM + tn]) = r1;
    }
}

// ---------------------------------------------------------------------------
// Tensor-core flash attention, tf32 mma.sync with 3xTF32 precision recovery.
// grid (TSEQ/QTILE, BATCH), block 128 (4 warps x m16 query rows).
// smem: K tile [64][PSTR], V^T tile [64][PSTR], P per-warp [16][PSTR].
// ---------------------------------------------------------------------------
__global__ __launch_bounds__(128) void attn_mma_kernel(float* __restrict__ out)
{
    extern __shared__ float sm[];
    float* Ks = sm;                        // [KTILE][PSTR]
    float* Vt = sm + KTILE * PSTR;         // [HDIM][PSTR]  (V transposed: [h][key])
    float* Pw = sm + 2 * KTILE * PSTR;     // [4][16][PSTR]

    const int b   = blockIdx.y;
    const int tid = threadIdx.x;
    const int w   = tid >> 5;
    const int ln  = tid & 31;
    const int g   = ln >> 2;     // 0..7
    const int tg  = ln & 3;      // 0..3

    const int r0 = blockIdx.x * QTILE + w * 16;   // warp's first query row
    float* Pme = Pw + w * 16 * PSTR;

    // ---- load Q fragments (persistent, hi/lo split) ----
    float qh[8][4], ql[8][4];
    {
        const float* q0 = &g_q[((long)b * TSEQ + r0 + g) * HDIM];
        const float* q1 = &g_q[((long)b * TSEQ + r0 + g + 8) * HDIM];
        #pragma unroll
        for (int k = 0; k < 8; k++) {
            float v0 = q0[k * 8 + tg];
            float v1 = q1[k * 8 + tg];
            float v2 = q0[k * 8 + tg + 4];
            float v3 = q1[k * 8 + tg + 4];
            qh[k][0] = tf32_hi(v0); ql[k][0] = v0 - qh[k][0];
            qh[k][1] = tf32_hi(v1); ql[k][1] = v1 - qh[k][1];
            qh[k][2] = tf32_hi(v2); ql[k][2] = v2 - qh[k][2];
            qh[k][3] = tf32_hi(v3); ql[k][3] = v3 - qh[k][3];
        }
    }

    float o[8][4];
    #pragma unroll
    for (int n = 0; n < 8; n++)
        #pragma unroll
        for (int i = 0; i < 4; i++) o[n][i] = 0.0f;
    float m0 = -1e30f, m1 = -1e30f, l0 = 0.0f, l1 = 0.0f;

    const float* __restrict__ kb = &g_k[(long)b * TSEQ * HDIM];
    const float* __restrict__ vb = &g_v[(long)b * TSEQ * HDIM];

    for (int t0 = 0; t0 < TSEQ; t0 += KTILE) {
        __syncthreads();
        // ---- stage K tile [key][h] and V^T tile [h][key] ----
        #pragma unroll
        for (int p = 0; p < 8; p++) {
            const int id  = p * 128 + tid;       // 0..1023 float4s
            const int key = id >> 4;
            const int h4  = (id & 15) * 4;
            float4 kv = *reinterpret_cast<const float4*>(&kb[(long)(t0 + key) * HDIM + h4]);
            *reinterpret_cast<float4*>(&Ks[key * PSTR + h4]) = kv;
            float4 vv = *reinterpret_cast<const float4*>(&vb[(long)(t0 + key) * HDIM + h4]);
            Vt[(h4 + 0) * PSTR + key] = vv.x;
            Vt[(h4 + 1) * PSTR + key] = vv.y;
            Vt[(h4 + 2) * PSTR + key] = vv.z;
            Vt[(h4 + 3) * PSTR + key] = vv.w;
        }
        __syncthreads();

        // ---- S = Q K^T  (3xTF32) ----
        float s[8][4];
        #pragma unroll
        for (int n = 0; n < 8; n++)
            #pragma unroll
            for (int i = 0; i < 4; i++) s[n][i] = 0.0f;

        #pragma unroll
        for (int k = 0; k < 8; k++) {
            #pragma unroll
            for (int n = 0; n < 8; n++) {
                float kb0 = Ks[(n * 8 + g) * PSTR + k * 8 + tg];
                float kb1 = Ks[(n * 8 + g) * PSTR + k * 8 + tg + 4];
                float kh0 = tf32_hi(kb0), kl0 = kb0 - kh0;
                float kh1 = tf32_hi(kb1), kl1 = kb1 - kh1;
                mma_tf32(s[n][0], s[n][1], s[n][2], s[n][3],
                         qh[k][0], qh[k][1], qh[k][2], qh[k][3], kh0, kh1);
                mma_tf32(s[n][0], s[n][1], s[n][2], s[n][3],
                         ql[k][0], ql[k][1], ql[k][2], ql[k][3], kh0, kh1);
                mma_tf32(s[n][0], s[n][1], s[n][2], s[n][3],
                         qh[k][0], qh[k][1], qh[k][2], qh[k][3], kl0, kl1);
            }
        }

        // ---- online softmax ----
        float mx0 = -1e30f, mx1 = -1e30f;
        #pragma unroll
        for (int n = 0; n < 8; n++) {
            mx0 = fmaxf(mx0, fmaxf(s[n][0], s[n][1]));
            mx1 = fmaxf(mx1, fmaxf(s[n][2], s[n][3]));
        }
        mx0 = fmaxf(mx0, __shfl_xor_sync(0xffffffffu, mx0, 1));
        mx0 = fmaxf(mx0, __shfl_xor_sync(0xffffffffu, mx0, 2));
        mx1 = fmaxf(mx1, __shfl_xor_sync(0xffffffffu, mx1, 1));
        mx1 = fmaxf(mx1, __shfl_xor_sync(0xffffffffu, mx1, 2));

        const float nm0 = fmaxf(m0, mx0);
        const float nm1 = fmaxf(m1, mx1);
        const float al0 = __expf(m0 - nm0);
        const float al1 = __expf(m1 - nm1);
        m0 = nm0; m1 = nm1;
        l0 *= al0; l1 *= al1;
        #pragma unroll
        for (int n = 0; n < 8; n++) {
            o[n][0] *= al0; o[n][1] *= al0;
            o[n][2] *= al1; o[n][3] *= al1;
        }

        float ls0 = 0.0f, ls1 = 0.0f;
        #pragma unroll
        for (int n = 0; n < 8; n++) {
            float p0 = __expf(s[n][0] - nm0);
            float p1 = __expf(s[n][1] - nm0);
            float p2 = __expf(s[n][2] - nm1);
            float p3 = __expf(s[n][3] - nm1);
            ls0 += p0 + p1;
            ls1 += p2 + p3;
            Pme[g * PSTR + n * 8 + 2 * tg]           = p0;
            Pme[g * PSTR + n * 8 + 2 * tg + 1]       = p1;
            Pme[(g + 8) * PSTR + n * 8 + 2 * tg]     = p2;
            Pme[(g + 8) * PSTR + n * 8 + 2 * tg + 1] = p3;
        }
        ls0 += __shfl_xor_sync(0xffffffffu, ls0, 1);
        ls0 += __shfl_xor_sync(0xffffffffu, ls0, 2);
        ls1 += __shfl_xor_sync(0xffffffffu, ls1, 1);
        ls1 += __shfl_xor_sync(0xffffffffu, ls1, 2);
        l0 += ls0; l1 += ls1;
        __syncwarp();

        // ---- O += P V  (3xTF32) ----
        #pragma unroll
        for (int k = 0; k < 8; k++) {
            float a0 = Pme[g * PSTR + k * 8 + tg];
            float a1 = Pme[(g + 8) * PSTR + k * 8 + tg];
            float a2 = Pme[g * PSTR + k * 8 + tg + 4];
            float a3 = Pme[(g + 8) * PSTR + k * 8 + tg + 4];
            float ah0 = tf32_hi(a0), pl0 = a0 - ah0;
            float ah1 = tf32_hi(a1), pl1 = a1 - ah1;
            float ah2 = tf32_hi(a2), pl2 = a2 - ah2;
            float ah3 = tf32_hi(a3), pl3 = a3 - ah3;
            #pragma unroll
            for (int n = 0; n < 8; n++) {
                float vb0 = Vt[(n * 8 + g) * PSTR + k * 8 + tg];
                float vb1 = Vt[(n * 8 + g) * PSTR + k * 8 + tg + 4];
                float vh0 = tf32_hi(vb0), vl0 = vb0 - vh0;
                float vh1 = tf32_hi(vb1), vl1 = vb1 - vh1;
                mma_tf32(o[n][0], o[n][1], o[n][2], o[n][3],
                         ah0, ah1, ah2, ah3, vh0, vh1);
                mma_tf32(o[n][0], o[n][1], o[n][2], o[n][3],
                         pl0, pl1, pl2, pl3, vh0, vh1);
                mma_tf32(o[n][0], o[n][1], o[n][2], o[n][3],
                         ah0, ah1, ah2, ah3, vl0, vl1);
            }
        }
    }

    // ---- epilogue: normalize and store ----
    const float inv0 = 1.0f / l0;
    const float inv1 = 1.0f / l1;
    float* orow0 = &out[((long)b * TSEQ + r0 + g) * HDIM];
    float* orow1 = &out[((long)b * TSEQ + r0 + g + 8) * HDIM];
    #pragma unroll
    for (int n = 0; n < 8; n++) {
        float2 u0, u1;
        u0.x = o[n][0] * inv0; u0.y = o[n][1] * inv0;
        u1.x = o[n][2] * inv1; u1.y = o[n][3] * inv1;
        *reinterpret_cast<float2*>(&orow0[n * 8 + 2 * tg]) = u0;
        *reinterpret_cast<float2*>(&orow1[n * 8 + 2 * tg]) = u1;
    }
}

// ---------------------------------------------------------------------------
extern "C" void kernel_launch(void* const* d_in, const int* in_sizes, int n_in,
                              void* d_out, int out_size)
{
    const float* x  = (const float*)d_in[0];
    const float* Wq = (const float*)d_in[1];
    const float* Wk = (const float*)d_in[2];
    const float* Wv = (const float*)d_in[3];
    float* out = (float*)d_out;

    dim3 pg(BT_TOTAL / 128, 3);
    proj_kernel<<<pg, 256>>>(x, Wq, Wk, Wv);

    const int smem_bytes = (2 * KTILE * PSTR + 4 * 16 * PSTR) * sizeof(float); // 52224
    static bool attr_set = false;
    if (!attr_set) {
        cudaFuncSetAttribute(attn_mma_kernel,
                             cudaFuncAttributeMaxDynamicSharedMemorySize, smem_bytes);
        attr_set = true;
    }
    dim3 ag(TSEQ / QTILE, BATCH);
    attn_mma_kernel<<<ag, 128, smem_bytes>>>(out);
}

// round 6
// speedup vs baseline: 1.5941x; 1.1238x over previous
#include <cuda_runtime.h>

#define BATCH   4
#define TSEQ    4096
#define CDIM    512
#define HDIM    64
#define BT_TOTAL (BATCH * TSEQ)   // 16384
#define QTILE   64
#define KTILE   64

// packed tile row stride in float4 units (36*16B = 576B == 16 banks mod 32:
// phase groups of LDS.128 land conflict-free for the (g,tg) access pattern)
#define PK4STR  36
// P packed row stride in float2 units
#define PCSTR   68

typedef unsigned long long u64;

// ---- packed fp32x2 helpers (proj kernel) ----
__device__ __forceinline__ u64 ffma2(u64 a, u64 b, u64 c) {
    u64 d;
    asm("fma.rn.f32x2 %0, %1, %2, %3;" : "=l"(d) : "l"(a), "l"(b), "l"(c));
    return d;
}
__device__ __forceinline__ u64 bcast2(float x) {
    u64 d;
    asm("mov.b64 %0, {%1, %1};" : "=l"(d) : "f"(x));
    return d;
}
__device__ __forceinline__ void unpack2(u64 v, float& lo, float& hi) {
    asm("mov.b64 {%0, %1}, %2;" : "=f"(lo), "=f"(hi) : "l"(v));
}

// ---- tf32 helpers ----
__device__ __forceinline__ float tf32_hi(float a) {
    unsigned u;
    asm("cvt.rna.tf32.f32 %0, %1;" : "=r"(u) : "f"(a));
    return __uint_as_float(u);
}
__device__ __forceinline__ void mma_tf32(
    float& c0, float& c1, float& c2, float& c3,
    float a0, float a1, float a2, float a3,
    float b0, float b1)
{
    unsigned A0 = __float_as_uint(a0), A1 = __float_as_uint(a1);
    unsigned A2 = __float_as_uint(a2), A3 = __float_as_uint(a3);
    unsigned B0 = __float_as_uint(b0), B1 = __float_as_uint(b1);
    asm("mma.sync.aligned.m16n8k8.row.col.f32.tf32.tf32.f32 "
        "{%0,%1,%2,%3},{%4,%5,%6,%7},{%8,%9},{%0,%1,%2,%3};"
        : "+f"(c0), "+f"(c1), "+f"(c2), "+f"(c3)
        : "r"(A0), "r"(A1), "r"(A2), "r"(A3), "r"(B0), "r"(B1));
}

// Scratch (static device arrays per allocation rules).
__device__ float g_q[BT_TOTAL * HDIM];
__device__ float g_k[BT_TOTAL * HDIM];
__device__ float g_v[BT_TOTAL * HDIM];

// ---------------------------------------------------------------------------
// Projection GEMM (unchanged): out[16384,64] = x @ W, x3 matrices.
// ---------------------------------------------------------------------------
__global__ __launch_bounds__(256) void proj_kernel(
    const float* __restrict__ x,
    const float* __restrict__ Wq,
    const float* __restrict__ Wk,
    const float* __restrict__ Wv)
{
    const int mat = blockIdx.y;
    const float* __restrict__ W = (mat == 0) ? Wq : (mat == 1) ? Wk : Wv;
    float* __restrict__ out     = (mat == 0) ? g_q : (mat == 1) ? g_k : g_v;
    const int row0 = blockIdx.x * 128;

    __shared__ float As[32][132];
    __shared__ float Bs[32][64];

    const int tid = threadIdx.x;
    const int tm = (tid / 16) * 8;
    const int tn = (tid % 16) * 4;

    u64 acc2[4][4];
    #pragma unroll
    for (int i = 0; i < 4; i++)
        #pragma unroll
        for (int j = 0; j < 4; j++) acc2[i][j] = 0ull;

    for (int k0 = 0; k0 < CDIM; k0 += 32) {
        {
            const int tr = tid / 8;
            const int tc = (tid % 8) * 4;
            #pragma unroll
            for (int p = 0; p < 4; p++) {
                const int r = tr + p * 32;
                float4 va = *reinterpret_cast<const float4*>(
                    &x[(long)(row0 + r) * CDIM + k0 + tc]);
                As[tc + 0][r] = va.x;
                As[tc + 1][r] = va.y;
                As[tc + 2][r] = va.z;
                As[tc + 3][r] = va.w;
            }
        }
        {
            const int tr = tid / 16;
            const int tc = (tid % 16) * 4;
            #pragma unroll
            for (int p = 0; p < 2; p++) {
                const int r = tr + p * 16;
                *reinterpret_cast<float4*>(&Bs[r][tc]) =
                    *reinterpret_cast<const float4*>(&W[(long)(k0 + r) * HDIM + tc]);
            }
        }
        __syncthreads();

        #pragma unroll
        for (int kk = 0; kk < 32; kk++) {
            const ulonglong2* arow =
                reinterpret_cast<const ulonglong2*>(&As[kk][tm]);
            ulonglong2 a01 = arow[0];
            ulonglong2 a23 = arow[1];
            u64 a2[4] = {a01.x, a01.y, a23.x, a23.y};
            float4 bv = *reinterpret_cast<const float4*>(&Bs[kk][tn]);
            u64 b2[4] = {bcast2(bv.x), bcast2(bv.y), bcast2(bv.z), bcast2(bv.w)};
            #pragma unroll
            for (int i = 0; i < 4; i++)
                #pragma unroll
                for (int j = 0; j < 4; j++)
                    acc2[i][j] = ffma2(a2[i], b2[j], acc2[i][j]);
        }
        __syncthreads();
    }

    const float scale = (mat == 0) ? 8.0f : 1.0f;
    #pragma unroll
    for (int i = 0; i < 4; i++) {
        float lo[4], hi[4];
        #pragma unroll
        for (int j = 0; j < 4; j++) unpack2(acc2[i][j], lo[j], hi[j]);
        float4 r0, r1;
        r0.x = lo[0] * scale; r0.y = lo[1] * scale; r0.z = lo[2] * scale; r0.w = lo[3] * scale;
        r1.x = hi[0] * scale; r1.y = hi[1] * scale; r1.z = hi[2] * scale; r1.w = hi[3] * scale;
        *reinterpret_cast<float4*>(&out[(long)(row0 + tm + 2 * i + 0) * HDIM + tn]) = r0;
        *reinterpret_cast<float4*>(&out[(long)(row0 + tm + 2 * i + 1) * HDIM + tn]) = r1;
    }
}

// ---------------------------------------------------------------------------
// Tensor-core flash attention, 3xTF32, split-packed B tiles.
// grid (TSEQ/QTILE, BATCH), block 128 (4 warps x m16 query rows).
// smem:
//   KP4[key][j] float4 = {hi(K[key][k8+tg]), hi(K[key][k8+tg+4]), lo(..), lo(..)}
//     with j = k*4+tg, row stride PK4STR float4.
//   VP4[h][j]   float4 = {hi(V[k8+tg][h]),  hi(V[k8+tg+4][h]),  lo(..), lo(..)}
//   Ppk[warp][g][col] float2 = {P[g][col], P[g+8][col]}, row stride PCSTR.
// Inner loops: 1 LDS.128 + 3 mma per (k,n) step.
// ---------------------------------------------------------------------------
__global__ __launch_bounds__(128) void attn_mma_kernel(float* __restrict__ out)
{
    extern __shared__ float4 sm4[];
    float4* KP4 = sm4;                                   // 64*PK4STR float4
    float4* VP4 = sm4 + KTILE * PK4STR;                  // 64*PK4STR float4
    float2* Ppk = reinterpret_cast<float2*>(sm4 + 2 * KTILE * PK4STR);

    const int b   = blockIdx.y;
    const int tid = threadIdx.x;
    const int w   = tid >> 5;
    const int ln  = tid & 31;
    const int g   = ln >> 2;     // 0..7
    const int tg  = ln & 3;      // 0..3

    const int r0 = blockIdx.x * QTILE + w * 16;
    float2* Pme = Ppk + (w * 8 + g) * PCSTR;             // this thread's P row base

    // ---- load Q fragments (persistent, hi/lo split) ----
    float qh[8][4], ql[8][4];
    {
        const float* q0 = &g_q[((long)b * TSEQ + r0 + g) * HDIM];
        const float* q1 = &g_q[((long)b * TSEQ + r0 + g + 8) * HDIM];
        #pragma unroll
        for (int k = 0; k < 8; k++) {
            float v0 = q0[k * 8 + tg];
            float v1 = q1[k * 8 + tg];
            float v2 = q0[k * 8 + tg + 4];
            float v3 = q1[k * 8 + tg + 4];
            qh[k][0] = tf32_hi(v0); ql[k][0] = v0 - qh[k][0];
            qh[k][1] = tf32_hi(v1); ql[k][1] = v1 - qh[k][1];
            qh[k][2] = tf32_hi(v2); ql[k][2] = v2 - qh[k][2];
            qh[k][3] = tf32_hi(v3); ql[k][3] = v3 - qh[k][3];
        }
    }

    float o[8][4];
    #pragma unroll
    for (int n = 0; n < 8; n++)
        #pragma unroll
        for (int i = 0; i < 4; i++) o[n][i] = 0.0f;
    float m0 = -1e30f, m1 = -1e30f, l0 = 0.0f, l1 = 0.0f;

    const float* __restrict__ kb = &g_k[(long)b * TSEQ * HDIM];
    const float* __restrict__ vb = &g_v[(long)b * TSEQ * HDIM];

    for (int t0 = 0; t0 < TSEQ; t0 += KTILE) {
        __syncthreads();
        // ---- stage K tile: split + pack into B-fragment order ----
        #pragma unroll
        for (int p = 0; p < 4; p++) {
            const int task = p * 128 + tid;        // 0..511
            const int key  = task >> 3;
            const int c    = task & 7;             // k-block
            const float* krow = &kb[(long)(t0 + key) * HDIM + c * 8];
            float4 fa = *reinterpret_cast<const float4*>(krow);
            float4 fb = *reinterpret_cast<const float4*>(krow + 4);
            float4* dst = &KP4[key * PK4STR + c * 4];
            float a_[4] = {fa.x, fa.y, fa.z, fa.w};
            float b_[4] = {fb.x, fb.y, fb.z, fb.w};
            #pragma unroll
            for (int q = 0; q < 4; q++) {
                float ha = tf32_hi(a_[q]);
                float hb = tf32_hi(b_[q]);
                dst[q] = make_float4(ha, hb, a_[q] - ha, b_[q] - hb);
            }
        }
        // ---- stage V tile (transposed): split + pack ----
        #pragma unroll
        for (int p = 0; p < 4; p++) {
            const int task = p * 128 + tid;        // 0..511
            const int bk   = task >> 4;            // 0..31 base-key index
            const int h4   = (task & 15) * 4;      // 0..60
            const int kk   = bk >> 2;
            const int tt   = bk & 3;
            const int keyA = kk * 8 + tt;
            const int j    = kk * 4 + tt;
            const float* vra = &vb[(long)(t0 + keyA) * HDIM + h4];
            const float* vrb = &vb[(long)(t0 + keyA + 4) * HDIM + h4];
            float4 fa = *reinterpret_cast<const float4*>(vra);
            float4 fb = *reinterpret_cast<const float4*>(vrb);
            float a_[4] = {fa.x, fa.y, fa.z, fa.w};
            float b_[4] = {fb.x, fb.y, fb.z, fb.w};
            #pragma unroll
            for (int q = 0; q < 4; q++) {
                float ha = tf32_hi(a_[q]);
                float hb = tf32_hi(b_[q]);
                VP4[(h4 + q) * PK4STR + j] =
                    make_float4(ha, hb, a_[q] - ha, b_[q] - hb);
            }
        }
        __syncthreads();

        // ---- S = Q K^T  (3xTF32): 1 LDS.128 + 3 mma per step ----
        float s[8][4];
        #pragma unroll
        for (int n = 0; n < 8; n++)
            #pragma unroll
            for (int i = 0; i < 4; i++) s[n][i] = 0.0f;

        #pragma unroll
        for (int k = 0; k < 8; k++) {
            const float4* kbase = &KP4[g * PK4STR + k * 4 + tg];
            #pragma unroll
            for (int n = 0; n < 8; n++) {
                float4 kp = kbase[n * 8 * PK4STR];
                mma_tf32(s[n][0], s[n][1], s[n][2], s[n][3],
                         qh[k][0], qh[k][1], qh[k][2], qh[k][3], kp.x, kp.y);
                mma_tf32(s[n][0], s[n][1], s[n][2], s[n][3],
                         ql[k][0], ql[k][1], ql[k][2], ql[k][3], kp.x, kp.y);
                mma_tf32(s[n][0], s[n][1], s[n][2], s[n][3],
                         qh[k][0], qh[k][1], qh[k][2], qh[k][3], kp.z, kp.w);
            }
        }

        // ---- online softmax ----
        float mx0 = -1e30f, mx1 = -1e30f;
        #pragma unroll
        for (int n = 0; n < 8; n++) {
            mx0 = fmaxf(mx0, fmaxf(s[n][0], s[n][1]));
            mx1 = fmaxf(mx1, fmaxf(s[n][2], s[n][3]));
        }
        mx0 = fmaxf(mx0, __shfl_xor_sync(0xffffffffu, mx0, 1));
        mx0 = fmaxf(mx0, __shfl_xor_sync(0xffffffffu, mx0, 2));
        mx1 = fmaxf(mx1, __shfl_xor_sync(0xffffffffu, mx1, 1));
        mx1 = fmaxf(mx1, __shfl_xor_sync(0xffffffffu, mx1, 2));

        const float nm0 = fmaxf(m0, mx0);
        const float nm1 = fmaxf(m1, mx1);
        const float al0 = __expf(m0 - nm0);
        const float al1 = __expf(m1 - nm1);
        m0 = nm0; m1 = nm1;
        l0 *= al0; l1 *= al1;
        #pragma unroll
        for (int n = 0; n < 8; n++) {
            o[n][0] *= al0; o[n][1] *= al0;
            o[n][2] *= al1; o[n][3] *= al1;
        }

        float ls0 = 0.0f, ls1 = 0.0f;
        #pragma unroll
        for (int n = 0; n < 8; n++) {
            float p0 = __expf(s[n][0] - nm0);
            float p1 = __expf(s[n][1] - nm0);
            float p2 = __expf(s[n][2] - nm1);
            float p3 = __expf(s[n][3] - nm1);
            ls0 += p0 + p1;
            ls1 += p2 + p3;
            Pme[n * 8 + 2 * tg]     = make_float2(p0, p2);
            Pme[n * 8 + 2 * tg + 1] = make_float2(p1, p3);
        }
        ls0 += __shfl_xor_sync(0xffffffffu, ls0, 1);
        ls0 += __shfl_xor_sync(0xffffffffu, ls0, 2);
        ls1 += __shfl_xor_sync(0xffffffffu, ls1, 1);
        ls1 += __shfl_xor_sync(0xffffffffu, ls1, 2);
        l0 += ls0; l1 += ls1;
        __syncwarp();

        // ---- O += P V  (3xTF32) ----
        #pragma unroll
        for (int k = 0; k < 8; k++) {
            float2 pA = Pme[k * 8 + tg];        // {P[g][key], P[g+8][key]}
            float2 pB = Pme[k * 8 + tg + 4];
            float ah0 = tf32_hi(pA.x), al0_ = pA.x - ah0;
            float ah1 = tf32_hi(pA.y), al1_ = pA.y - ah1;
            float ah2 = tf32_hi(pB.x), al2_ = pB.x - ah2;
            float ah3 = tf32_hi(pB.y), al3_ = pB.y - ah3;
            const float4* vbase = &VP4[g * PK4STR + k * 4 + tg];
            #pragma unroll
            for (int n = 0; n < 8; n++) {
                float4 vp = vbase[n * 8 * PK4STR];
                mma_tf32(o[n][0], o[n][1], o[n][2], o[n][3],
                         ah0, ah1, ah2, ah3, vp.x, vp.y);
                mma_tf32(o[n][0], o[n][1], o[n][2], o[n][3],
                         al0_, al1_, al2_, al3_, vp.x, vp.y);
                mma_tf32(o[n][0], o[n][1], o[n][2], o[n][3],
                         ah0, ah1, ah2, ah3, vp.z, vp.w);
            }
        }
    }

    // ---- epilogue ----
    const float inv0 = 1.0f / l0;
    const float inv1 = 1.0f / l1;
    float* orow0 = &out[((long)b * TSEQ + r0 + g) * HDIM];
    float* orow1 = &out[((long)b * TSEQ + r0 + g + 8) * HDIM];
    #pragma unroll
    for (int n = 0; n < 8; n++) {
        float2 u0, u1;
        u0.x = o[n][0] * inv0; u0.y = o[n][1] * inv0;
        u1.x = o[n][2] * inv1; u1.y = o[n][3] * inv1;
        *reinterpret_cast<float2*>(&orow0[n * 8 + 2 * tg]) = u0;
        *reinterpret_cast<float2*>(&orow1[n * 8 + 2 * tg]) = u1;
    }
}

// ---------------------------------------------------------------------------
extern "C" void kernel_launch(void* const* d_in, const int* in_sizes, int n_in,
                              void* d_out, int out_size)
{
    const float* x  = (const float*)d_in[0];
    const float* Wq = (const float*)d_in[1];
    const float* Wk = (const float*)d_in[2];
    const float* Wv = (const float*)d_in[3];
    float* out = (float*)d_out;

    dim3 pg(BT_TOTAL / 128, 3);
    proj_kernel<<<pg, 256>>>(x, Wq, Wk, Wv);

    const int smem_bytes = 2 * KTILE * PK4STR * 16 + 4 * 8 * PCSTR * 8; // 91136
    static bool attr_set = false;
    if (!attr_set) {
        cudaFuncSetAttribute(attn_mma_kernel,
                             cudaFuncAttributeMaxDynamicSharedMemorySize, smem_bytes);
        attr_set = true;
    }
    dim3 ag(TSEQ / QTILE, BATCH);
    attn_mma_kernel<<<ag, 128, smem_bytes>>>(out);
}

// round 9
// speedup vs baseline: 1.7305x; 1.0856x over previous
#include <cuda_runtime.h>
#include <cstdint>

#define BATCH   4
#define TSEQ    4096
#define CDIM    512
#define HDIM    64
#define BT_TOTAL (BATCH * TSEQ)   // 16384
#define QTILE   128
#define KTILE   32
#define NSPLIT  2
#define KEYS_PER_SPLIT (TSEQ / NSPLIT)     // 2048
#define NT      (KEYS_PER_SPLIT / KTILE)   // 64

#define KSTR4   36   // K row stride (float4): 32 entries used (8 k-blocks x 4)
#define VSTR4   20   // V^T row stride (float4): 16 entries used (4 key-blocks x 4)

typedef unsigned long long u64;

// ---- packed fp32x2 helpers (proj kernel) ----
__device__ __forceinline__ u64 ffma2(u64 a, u64 b, u64 c) {
    u64 d;
    asm("fma.rn.f32x2 %0, %1, %2, %3;" : "=l"(d) : "l"(a), "l"(b), "l"(c));
    return d;
}
__device__ __forceinline__ u64 bcast2(float x) {
    u64 d;
    asm("mov.b64 %0, {%1, %1};" : "=l"(d) : "f"(x));
    return d;
}
__device__ __forceinline__ void unpack2(u64 v, float& lo, float& hi) {
    asm("mov.b64 {%0, %1}, %2;" : "=f"(lo), "=f"(hi) : "l"(v));
}

// ---- tf32 helpers ----
__device__ __forceinline__ float tf32_hi(float a) {
    unsigned u;
    asm("cvt.rna.tf32.f32 %0, %1;" : "=r"(u) : "f"(a));
    return __uint_as_float(u);
}
__device__ __forceinline__ void mma_tf32(
    float& c0, float& c1, float& c2, float& c3,
    float a0, float a1, float a2, float a3,
    float b0, float b1)
{
    unsigned A0 = __float_as_uint(a0), A1 = __float_as_uint(a1);
    unsigned A2 = __float_as_uint(a2), A3 = __float_as_uint(a3);
    unsigned B0 = __float_as_uint(b0), B1 = __float_as_uint(b1);
    asm("mma.sync.aligned.m16n8k8.row.col.f32.tf32.tf32.f32 "
        "{%0,%1,%2,%3},{%4,%5,%6,%7},{%8,%9},{%0,%1,%2,%3};"
        : "+f"(c0), "+f"(c1), "+f"(c2), "+f"(c3)
        : "r"(A0), "r"(A1), "r"(A2), "r"(A3), "r"(B0), "r"(B1));
}

// Scratch (static device arrays per allocation rules).
__device__ float g_q[BT_TOTAL * HDIM];
__device__ float g_k[BT_TOTAL * HDIM];
__device__ float g_v[BT_TOTAL * HDIM];
// split-KV partials
__device__ float g_pacc[NSPLIT][BT_TOTAL][HDIM];
__device__ float g_pm[NSPLIT][BT_TOTAL];
__device__ float g_pl[NSPLIT][BT_TOTAL];

// ---------------------------------------------------------------------------
// Projection GEMM (unchanged from R5).
// ---------------------------------------------------------------------------
__global__ __launch_bounds__(256) void proj_kernel(
    const float* __restrict__ x,
    const float* __restrict__ Wq,
    const float* __restrict__ Wk,
    const float* __restrict__ Wv)
{
    const int mat = blockIdx.y;
    const float* __restrict__ W = (mat == 0) ? Wq : (mat == 1) ? Wk : Wv;
    float* __restrict__ out     = (mat == 0) ? g_q : (mat == 1) ? g_k : g_v;
    const int row0 = blockIdx.x * 128;

    __shared__ float As[32][132];
    __shared__ float Bs[32][64];

    const int tid = threadIdx.x;
    const int tm = (tid / 16) * 8;
    const int tn = (tid % 16) * 4;

    u64 acc2[4][4];
    #pragma unroll
    for (int i = 0; i < 4; i++)
        #pragma unroll
        for (int j = 0; j < 4; j++) acc2[i][j] = 0ull;

    for (int k0 = 0; k0 < CDIM; k0 += 32) {
        {
            const int tr = tid / 8;
            const int tc = (tid % 8) * 4;
            #pragma unroll
            for (int p = 0; p < 4; p++) {
                const int r = tr + p * 32;
                float4 va = *reinterpret_cast<const float4*>(
                    &x[(long)(row0 + r) * CDIM + k0 + tc]);
                As[tc + 0][r] = va.x;
                As[tc + 1][r] = va.y;
                As[tc + 2][r] = va.z;
                As[tc + 3][r] = va.w;
            }
        }
        {
            const int tr = tid / 16;
            const int tc = (tid % 16) * 4;
            #pragma unroll
            for (int p = 0; p < 2; p++) {
                const int r = tr + p * 16;
                *reinterpret_cast<float4*>(&Bs[r][tc]) =
                    *reinterpret_cast<const float4*>(&W[(long)(k0 + r) * HDIM + tc]);
            }
        }
        __syncthreads();

        #pragma unroll
        for (int kk = 0; kk < 32; kk++) {
            const ulonglong2* arow =
                reinterpret_cast<const ulonglong2*>(&As[kk][tm]);
            ulonglong2 a01 = arow[0];
            ulonglong2 a23 = arow[1];
            u64 a2[4] = {a01.x, a01.y, a23.x, a23.y};
            float4 bv = *reinterpret_cast<const float4*>(&Bs[kk][tn]);
            u64 b2[4] = {bcast2(bv.x), bcast2(bv.y), bcast2(bv.z), bcast2(bv.w)};
            #pragma unroll
            for (int i = 0; i < 4; i++)
                #pragma unroll
                for (int j = 0; j < 4; j++)
                    acc2[i][j] = ffma2(a2[i], b2[j], acc2[i][j]);
        }
        __syncthreads();
    }

    const float scale = (mat == 0) ? 8.0f : 1.0f;
    #pragma unroll
    for (int i = 0; i < 4; i++) {
        float lo[4], hi[4];
        #pragma unroll
        for (int j = 0; j < 4; j++) unpack2(acc2[i][j], lo[j], hi[j]);
        float4 r0, r1;
        r0.x = lo[0] * scale; r0.y = lo[1] * scale; r0.z = lo[2] * scale; r0.w = lo[3] * scale;
        r1.x = hi[0] * scale; r1.y = hi[1] * scale; r1.z = hi[2] * scale; r1.w = hi[3] * scale;
        *reinterpret_cast<float4*>(&out[(long)(row0 + tm + 2 * i + 0) * HDIM + tn]) = r0;
        *reinterpret_cast<float4*>(&out[(long)(row0 + tm + 2 * i + 1) * HDIM + tn]) = r1;
    }
}

// ---------------------------------------------------------------------------
// mma.sync flash attention, 3xTF32, m32-per-warp (2 A-tiles share each B LDS).
// grid (TSEQ/QTILE, BATCH, NSPLIT), block 128 (4 warps x 32 q-rows).
// smem (float4 units):
//   KP4[32 keys][KSTR4]    : {hiA,hiB,loA,loB} B-fragments of K  (1152 f4)
//   VP4[64 h  ][VSTR4]     : same for V^T                        (1280 f4)
//   QA [8 mb][256]         : raw A-fragment-packed Q             (2048 f4)
//   P2 [8 mb][32c][8g] f2  : raw P pairs {row g, row g+8}        (1024 f4)
// ---------------------------------------------------------------------------
__global__ __launch_bounds__(128) void attn_mma_kernel()
{
    extern __shared__ float4 sm4[];
    float4* KP4 = sm4;                        // 1152 f4
    float4* VP4 = sm4 + 1152;                 // 1280 f4
    float4* QA  = sm4 + 2432;                 // 2048 f4
    float2* P2  = reinterpret_cast<float2*>(sm4 + 4480);  // 2048 f2

    const int b     = blockIdx.y;
    const int split = blockIdx.z;
    const int q0    = blockIdx.x * QTILE;
    const int tid   = threadIdx.x;
    const int w     = tid >> 5;
    const int ln    = tid & 31;
    const int g     = ln >> 2;
    const int tg    = ln & 3;

    const float* __restrict__ kb = &g_k[(long)b * TSEQ * HDIM];
    const float* __restrict__ vb = &g_v[(long)b * TSEQ * HDIM];

    // ---- stage Q (raw, A-fragment packed): entry e = mb*256 + k*32 + tg2*8 + g2
    //      content {Q(r,c), Q(r+8,c), Q(r,c+4), Q(r+8,c+4)},
    //      r = (mb>>1)*32 + (mb&1)*16 + g2, c = k*8+tg2.
    #pragma unroll
    for (int i = 0; i < 16; i++) {
        const int e  = tid * 16 + i;
        const int mb = e >> 8;
        const int k  = (e >> 5) & 7;
        const int t2 = (e >> 3) & 3;
        const int g2 = e & 7;
        const int r  = (mb >> 1) * 32 + (mb & 1) * 16 + g2;
        const int c  = k * 8 + t2;
        const float* q0p = &g_q[((long)b * TSEQ + q0 + r) * HDIM];
        const float* q1p = &g_q[((long)b * TSEQ + q0 + r + 8) * HDIM];
        QA[e] = make_float4(q0p[c], q1p[c], q0p[c + 4], q1p[c + 4]);
    }

    float o[2][8][4];
    #pragma unroll
    for (int m = 0; m < 2; m++)
        #pragma unroll
        for (int n = 0; n < 8; n++)
            #pragma unroll
            for (int i = 0; i < 4; i++) o[m][n][i] = 0.0f;
    float mr[2][2], lr[2][2];
    #pragma unroll
    for (int m = 0; m < 2; m++) {
        mr[m][0] = mr[m][1] = -1e30f;
        lr[m][0] = lr[m][1] = 0.0f;
    }

    #pragma unroll 1
    for (int t = 0; t < NT; t++) {
        const int t0 = split * KEYS_PER_SPLIT + t * KTILE;
        __syncthreads();

        // ---- stage K (32 keys): 256 tasks, 2 per thread ----
        #pragma unroll
        for (int p = 0; p < 2; p++) {
            const int task = p * 128 + tid;
            const int key  = task >> 3;
            const int c    = task & 7;
            const float* kr = &kb[(long)(t0 + key) * HDIM + c * 8];
            float4 fa = *reinterpret_cast<const float4*>(kr);
            float4 fb = *reinterpret_cast<const float4*>(kr + 4);
            float a_[4] = {fa.x, fa.y, fa.z, fa.w};
            float b_[4] = {fb.x, fb.y, fb.z, fb.w};
            float4* dst = &KP4[key * KSTR4 + c * 4];
            #pragma unroll
            for (int q = 0; q < 4; q++) {
                float ha = tf32_hi(a_[q]);
                float hb = tf32_hi(b_[q]);
                dst[q] = make_float4(ha, hb, a_[q] - ha, b_[q] - hb);
            }
        }
        // ---- stage V^T: 256 tasks ----
        #pragma unroll
        for (int p = 0; p < 2; p++) {
            const int task = p * 128 + tid;
            const int bk   = task >> 4;            // 0..15
            const int h4   = (task & 15) * 4;
            const int kk   = bk >> 2;              // 0..3 key-block
            const int tt   = bk & 3;
            const int keyA = kk * 8 + tt;
            const float* va_ = &vb[(long)(t0 + keyA) * HDIM + h4];
            const float* vb_ = &vb[(long)(t0 + keyA + 4) * HDIM + h4];
            float4 fa = *reinterpret_cast<const float4*>(va_);
            float4 fb = *reinterpret_cast<const float4*>(vb_);
            float a_[4] = {fa.x, fa.y, fa.z, fa.w};
            float b_[4] = {fb.x, fb.y, fb.z, fb.w};
            #pragma unroll
            for (int q = 0; q < 4; q++) {
                float ha = tf32_hi(a_[q]);
                float hb = tf32_hi(b_[q]);
                VP4[(h4 + q) * VSTR4 + kk * 4 + tt] =
                    make_float4(ha, hb, a_[q] - ha, b_[q] - hb);
            }
        }
        __syncthreads();

        // ---- QK: S = Q K^T (3xTF32), B shared by both m-tiles ----
        float s[2][4][4];
        #pragma unroll
        for (int m = 0; m < 2; m++)
            #pragma unroll
            for (int n = 0; n < 4; n++)
                #pragma unroll
                for (int i = 0; i < 4; i++) s[m][n][i] = 0.0f;

        #pragma unroll
        for (int k = 0; k < 8; k++) {
            float qh[2][4], ql[2][4];
            #pragma unroll
            for (int m = 0; m < 2; m++) {
                float4 qa = QA[(w * 2 + m) * 256 + k * 32 + tg * 8 + g];
                float v_[4] = {qa.x, qa.y, qa.z, qa.w};
                #pragma unroll
                for (int q = 0; q < 4; q++) {
                    qh[m][q] = tf32_hi(v_[q]);
                    ql[m][q] = v_[q] - qh[m][q];
                }
            }
            const float4* kbase = &KP4[g * KSTR4 + k * 4 + tg];
            #pragma unroll
            for (int n = 0; n < 4; n++) {
                float4 kp = kbase[n * 8 * KSTR4];
                #pragma unroll
                for (int m = 0; m < 2; m++) {
                    mma_tf32(s[m][n][0], s[m][n][1], s[m][n][2], s[m][n][3],
                             qh[m][0], qh[m][1], qh[m][2], qh[m][3], kp.x, kp.y);
                    mma_tf32(s[m][n][0], s[m][n][1], s[m][n][2], s[m][n][3],
                             ql[m][0], ql[m][1], ql[m][2], ql[m][3], kp.x, kp.y);
                    mma_tf32(s[m][n][0], s[m][n][1], s[m][n][2], s[m][n][3],
                             qh[m][0], qh[m][1], qh[m][2], qh[m][3], kp.z, kp.w);
                }
            }
        }

        // ---- online softmax (per m-tile, rows g / g+8) ----
        #pragma unroll
        for (int m = 0; m < 2; m++) {
            const int mb = w * 2 + m;
            float mxA = -1e30f, mxB = -1e30f;
            #pragma unroll
            for (int n = 0; n < 4; n++) {
                mxA = fmaxf(mxA, fmaxf(s[m][n][0], s[m][n][1]));
                mxB = fmaxf(mxB, fmaxf(s[m][n][2], s[m][n][3]));
            }
            mxA = fmaxf(mxA, __shfl_xor_sync(0xffffffffu, mxA, 1));
            mxA = fmaxf(mxA, __shfl_xor_sync(0xffffffffu, mxA, 2));
            mxB = fmaxf(mxB, __shfl_xor_sync(0xffffffffu, mxB, 1));
            mxB = fmaxf(mxB, __shfl_xor_sync(0xffffffffu, mxB, 2));

            const float nmA = fmaxf(mr[m][0], mxA);
            const float nmB = fmaxf(mr[m][1], mxB);
            const float alA = __expf(mr[m][0] - nmA);
            const float alB = __expf(mr[m][1] - nmB);
            mr[m][0] = nmA; mr[m][1] = nmB;

            float lsA = 0.0f, lsB = 0.0f;
            #pragma unroll
            for (int n = 0; n < 4; n++) {
                float p0 = __expf(s[m][n][0] - nmA);
                float p1 = __expf(s[m][n][1] - nmA);
                float p2 = __expf(s[m][n][2] - nmB);
                float p3 = __expf(s[m][n][3] - nmB);
                lsA += p0 + p1;
                lsB += p2 + p3;
                const int c = n * 8 + 2 * tg;
                P2[mb * 256 + c * 8 + g]       = make_float2(p0, p2);
                P2[mb * 256 + (c + 1) * 8 + g] = make_float2(p1, p3);
            }
            lsA += __shfl_xor_sync(0xffffffffu, lsA, 1);
            lsA += __shfl_xor_sync(0xffffffffu, lsA, 2);
            lsB += __shfl_xor_sync(0xffffffffu, lsB, 1);
            lsB += __shfl_xor_sync(0xffffffffu, lsB, 2);
            lr[m][0] = lr[m][0] * alA + lsA;
            lr[m][1] = lr[m][1] * alB + lsB;

            #pragma unroll
            for (int n = 0; n < 8; n++) {
                o[m][n][0] *= alA; o[m][n][1] *= alA;
                o[m][n][2] *= alB; o[m][n][3] *= alB;
            }
        }
        __syncwarp();

        // ---- PV: O += P V (3xTF32), V shared by both m-tiles ----
        #pragma unroll
        for (int k = 0; k < 4; k++) {
            float ah[2][4], al[2][4];
            #pragma unroll
            for (int m = 0; m < 2; m++) {
                const int mb = w * 2 + m;
                float2 pA = P2[mb * 256 + (k * 8 + tg) * 8 + g];
                float2 pB = P2[mb * 256 + (k * 8 + tg + 4) * 8 + g];
                float v_[4] = {pA.x, pA.y, pB.x, pB.y};
                #pragma unroll
                for (int q = 0; q < 4; q++) {
                    ah[m][q] = tf32_hi(v_[q]);
                    al[m][q] = v_[q] - ah[m][q];
                }
            }
            const float4* vbase = &VP4[g * VSTR4 + k * 4 + tg];
            #pragma unroll
            for (int n = 0; n < 8; n++) {
                float4 vp = vbase[n * 8 * VSTR4];
                #pragma unroll
                for (int m = 0; m < 2; m++) {
                    mma_tf32(o[m][n][0], o[m][n][1], o[m][n][2], o[m][n][3],
                             ah[m][0], ah[m][1], ah[m][2], ah[m][3], vp.x, vp.y);
                    mma_tf32(o[m][n][0], o[m][n][1], o[m][n][2], o[m][n][3],
                             al[m][0], al[m][1], al[m][2], al[m][3], vp.x, vp.y);
                    mma_tf32(o[m][n][0], o[m][n][1], o[m][n][2], o[m][n][3],
                             ah[m][0], ah[m][1], ah[m][2], ah[m][3], vp.z, vp.w);
                }
            }
        }
    }

    // ---- epilogue: write unnormalized partials + (m, l) ----
    #pragma unroll
    for (int m = 0; m < 2; m++) {
        const long rowA = (long)b * TSEQ + q0 + w * 32 + m * 16 + g;
        const long rowB = rowA + 8;
        #pragma unroll
        for (int n = 0; n < 8; n++) {
            const int c = n * 8 + 2 * tg;
            *reinterpret_cast<float2*>(&g_pacc[split][rowA][c]) =
                make_float2(o[m][n][0], o[m][n][1]);
            *reinterpret_cast<float2*>(&g_pacc[split][rowB][c]) =
                make_float2(o[m][n][2], o[m][n][3]);
        }
        if (tg == 0) {
            g_pm[split][rowA] = mr[m][0];
            g_pl[split][rowA] = lr[m][0];
            g_pm[split][rowB] = mr[m][1];
            g_pl[split][rowB] = lr[m][1];
        }
    }
}

// ---------------------------------------------------------------------------
// Combine split-KV partials.
// ---------------------------------------------------------------------------
__global__ __launch_bounds__(128) void combine_kernel(float* __restrict__ out)
{
    const long row = (long)blockIdx.x * 128 + threadIdx.x;

    float m[NSPLIT], w[NSPLIT];
    float M = -1e30f;
    #pragma unroll
    for (int i = 0; i < NSPLIT; i++) {
        m[i] = g_pm[i][row];
        M = fmaxf(M, m[i]);
    }
    float L = 0.0f;
    #pragma unroll
    for (int i = 0; i < NSPLIT; i++) {
        w[i] = __expf(m[i] - M);
        L += w[i] * g_pl[i][row];
    }
    const float inv = 1.0f / L;

    float* __restrict__ orow = &out[row * HDIM];
    #pragma unroll
    for (int h = 0; h < HDIM; h += 4) {
        float4 a = make_float4(0.f, 0.f, 0.f, 0.f);
        #pragma unroll
        for (int i = 0; i < NSPLIT; i++) {
            float4 p = *reinterpret_cast<const float4*>(&g_pacc[i][row][h]);
            a.x += w[i] * p.x;
            a.y += w[i] * p.y;
            a.z += w[i] * p.z;
            a.w += w[i] * p.w;
        }
        a.x *= inv; a.y *= inv; a.z *= inv; a.w *= inv;
        *reinterpret_cast<float4*>(&orow[h]) = a;
    }
}

// ---------------------------------------------------------------------------
extern "C" void kernel_launch(void* const* d_in, const int* in_sizes, int n_in,
                              void* d_out, int out_size)
{
    const float* x  = (const float*)d_in[0];
    const float* Wq = (const float*)d_in[1];
    const float* Wk = (const float*)d_in[2];
    const float* Wv = (const float*)d_in[3];
    float* out = (float*)d_out;

    dim3 pg(BT_TOTAL / 128, 3);
    proj_kernel<<<pg, 256>>>(x, Wq, Wk, Wv);

    const int smem_bytes = 5504 * 16;   // 88,064 B
    static bool attr_set = false;
    if (!attr_set) {
        cudaFuncSetAttribute(attn_mma_kernel,
                             cudaFuncAttributeMaxDynamicSharedMemorySize, smem_bytes);
        attr_set = true;
    }
    dim3 ag(TSEQ / QTILE, BATCH, NSPLIT);
    attn_mma_kernel<<<ag, 128, smem_bytes>>>();

    combine_kernel<<<BT_TOTAL / 128, 128>>>(out);
}

// round 10
// speedup vs baseline: 2.0269x; 1.1713x over previous
#include <cuda_runtime.h>
#include <cstdint>

#define BATCH   4
#define TSEQ    4096
#define CDIM    512
#define HDIM    64
#define BT_TOTAL (BATCH * TSEQ)   // 16384
#define QTILE   128
#define KTILE   32
#define NSPLIT  2
#define KEYS_PER_SPLIT (TSEQ / NSPLIT)     // 2048
#define NT      (KEYS_PER_SPLIT / KTILE)   // 64

#define KSTR4   36   // K row stride (float4): 32 entries used (8 k-blocks x 4)
#define VSTR2   20   // V^T row stride (float2): 16 entries used (4 key-blocks x 4)

typedef unsigned long long u64;

// ---- packed fp32x2 helpers (proj kernel) ----
__device__ __forceinline__ u64 ffma2(u64 a, u64 b, u64 c) {
    u64 d;
    asm("fma.rn.f32x2 %0, %1, %2, %3;" : "=l"(d) : "l"(a), "l"(b), "l"(c));
    return d;
}
__device__ __forceinline__ u64 bcast2(float x) {
    u64 d;
    asm("mov.b64 %0, {%1, %1};" : "=l"(d) : "f"(x));
    return d;
}
__device__ __forceinline__ void unpack2(u64 v, float& lo, float& hi) {
    asm("mov.b64 {%0, %1}, %2;" : "=f"(lo), "=f"(hi) : "l"(v));
}

// ---- tf32 helpers ----
__device__ __forceinline__ float tf32_hi(float a) {
    unsigned u;
    asm("cvt.rna.tf32.f32 %0, %1;" : "=r"(u) : "f"(a));
    return __uint_as_float(u);
}
__device__ __forceinline__ void mma_tf32(
    float& c0, float& c1, float& c2, float& c3,
    float a0, float a1, float a2, float a3,
    float b0, float b1)
{
    unsigned A0 = __float_as_uint(a0), A1 = __float_as_uint(a1);
    unsigned A2 = __float_as_uint(a2), A3 = __float_as_uint(a3);
    unsigned B0 = __float_as_uint(b0), B1 = __float_as_uint(b1);
    asm("mma.sync.aligned.m16n8k8.row.col.f32.tf32.tf32.f32 "
        "{%0,%1,%2,%3},{%4,%5,%6,%7},{%8,%9},{%0,%1,%2,%3};"
        : "+f"(c0), "+f"(c1), "+f"(c2), "+f"(c3)
        : "r"(A0), "r"(A1), "r"(A2), "r"(A3), "r"(B0), "r"(B1));
}

// Scratch (static device arrays per allocation rules).
__device__ float g_q[BT_TOTAL * HDIM];
__device__ float g_k[BT_TOTAL * HDIM];
__device__ float g_v[BT_TOTAL * HDIM];
// split-KV partials
__device__ float g_pacc[NSPLIT][BT_TOTAL][HDIM];
__device__ float g_pm[NSPLIT][BT_TOTAL];
__device__ float g_pl[NSPLIT][BT_TOTAL];

// ---------------------------------------------------------------------------
// Projection GEMM (unchanged).
// ---------------------------------------------------------------------------
__global__ __launch_bounds__(256) void proj_kernel(
    const float* __restrict__ x,
    const float* __restrict__ Wq,
    const float* __restrict__ Wk,
    const float* __restrict__ Wv)
{
    const int mat = blockIdx.y;
    const float* __restrict__ W = (mat == 0) ? Wq : (mat == 1) ? Wk : Wv;
    float* __restrict__ out     = (mat == 0) ? g_q : (mat == 1) ? g_k : g_v;
    const int row0 = blockIdx.x * 128;

    __shared__ float As[32][132];
    __shared__ float Bs[32][64];

    const int tid = threadIdx.x;
    const int tm = (tid / 16) * 8;
    const int tn = (tid % 16) * 4;

    u64 acc2[4][4];
    #pragma unroll
    for (int i = 0; i < 4; i++)
        #pragma unroll
        for (int j = 0; j < 4; j++) acc2[i][j] = 0ull;

    for (int k0 = 0; k0 < CDIM; k0 += 32) {
        {
            const int tr = tid / 8;
            const int tc = (tid % 8) * 4;
            #pragma unroll
            for (int p = 0; p < 4; p++) {
                const int r = tr + p * 32;
                float4 va = *reinterpret_cast<const float4*>(
                    &x[(long)(row0 + r) * CDIM + k0 + tc]);
                As[tc + 0][r] = va.x;
                As[tc + 1][r] = va.y;
                As[tc + 2][r] = va.z;
                As[tc + 3][r] = va.w;
            }
        }
        {
            const int tr = tid / 16;
            const int tc = (tid % 16) * 4;
            #pragma unroll
            for (int p = 0; p < 2; p++) {
                const int r = tr + p * 16;
                *reinterpret_cast<float4*>(&Bs[r][tc]) =
                    *reinterpret_cast<const float4*>(&W[(long)(k0 + r) * HDIM + tc]);
            }
        }
        __syncthreads();

        #pragma unroll
        for (int kk = 0; kk < 32; kk++) {
            const ulonglong2* arow =
                reinterpret_cast<const ulonglong2*>(&As[kk][tm]);
            ulonglong2 a01 = arow[0];
            ulonglong2 a23 = arow[1];
            u64 a2[4] = {a01.x, a01.y, a23.x, a23.y};
            float4 bv = *reinterpret_cast<const float4*>(&Bs[kk][tn]);
            u64 b2[4] = {bcast2(bv.x), bcast2(bv.y), bcast2(bv.z), bcast2(bv.w)};
            #pragma unroll
            for (int i = 0; i < 4; i++)
                #pragma unroll
                for (int j = 0; j < 4; j++)
                    acc2[i][j] = ffma2(a2[i], b2[j], acc2[i][j]);
        }
        __syncthreads();
    }

    const float scale = (mat == 0) ? 8.0f : 1.0f;
    #pragma unroll
    for (int i = 0; i < 4; i++) {
        float lo[4], hi[4];
        #pragma unroll
        for (int j = 0; j < 4; j++) unpack2(acc2[i][j], lo[j], hi[j]);
        float4 r0, r1;
        r0.x = lo[0] * scale; r0.y = lo[1] * scale; r0.z = lo[2] * scale; r0.w = lo[3] * scale;
        r1.x = hi[0] * scale; r1.y = hi[1] * scale; r1.z = hi[2] * scale; r1.w = hi[3] * scale;
        *reinterpret_cast<float4*>(&out[(long)(row0 + tm + 2 * i + 0) * HDIM + tn]) = r0;
        *reinterpret_cast<float4*>(&out[(long)(row0 + tm + 2 * i + 1) * HDIM + tn]) = r1;
    }
}

// ---------------------------------------------------------------------------
// mma.sync flash attention. QK = 3xTF32, PV = 1xTF32 (precision budget:
// P in (0,1], V ~ N(0,1) -> norm rel_err ~2e-4, gate is 1e-3).
// grid (TSEQ/QTILE, BATCH, NSPLIT), block 128 (4 warps x 32 q-rows).
// smem (float4 units):
//   KP4[32 keys][KSTR4]  f4 : {hiA,hiB,loA,loB} B-frags of K    (1152 f4)
//   VP2[64 h  ][VSTR2]   f2 : {hiA,hiB} B-frags of V^T           (640 f4)
//   QA [8 mb][256]       f4 : raw A-fragment-packed Q           (2048 f4)
//   P2 [8 mb][32c][8g]   f2 : raw P pairs {row g, row g+8}      (1024 f4)
// ---------------------------------------------------------------------------
__global__ __launch_bounds__(128) void attn_mma_kernel()
{
    extern __shared__ float4 sm4[];
    float4* KP4 = sm4;                                     // 1152 f4
    float2* VP2 = reinterpret_cast<float2*>(sm4 + 1152);   // 1280 f2
    float4* QA  = sm4 + 1792;                              // 2048 f4
    float2* P2  = reinterpret_cast<float2*>(sm4 + 3840);   // 2048 f2

    const int b     = blockIdx.y;
    const int split = blockIdx.z;
    const int q0    = blockIdx.x * QTILE;
    const int tid   = threadIdx.x;
    const int w     = tid >> 5;
    const int ln    = tid & 31;
    const int g     = ln >> 2;
    const int tg    = ln & 3;

    const float* __restrict__ kb = &g_k[(long)b * TSEQ * HDIM];
    const float* __restrict__ vb = &g_v[(long)b * TSEQ * HDIM];

    // ---- stage Q (raw, A-fragment packed) ----
    #pragma unroll
    for (int i = 0; i < 16; i++) {
        const int e  = tid * 16 + i;
        const int mb = e >> 8;
        const int k  = (e >> 5) & 7;
        const int t2 = (e >> 3) & 3;
        const int g2 = e & 7;
        const int r  = (mb >> 1) * 32 + (mb & 1) * 16 + g2;
        const int c  = k * 8 + t2;
        const float* q0p = &g_q[((long)b * TSEQ + q0 + r) * HDIM];
        const float* q1p = &g_q[((long)b * TSEQ + q0 + r + 8) * HDIM];
        QA[e] = make_float4(q0p[c], q1p[c], q0p[c + 4], q1p[c + 4]);
    }

    float o[2][8][4];
    #pragma unroll
    for (int m = 0; m < 2; m++)
        #pragma unroll
        for (int n = 0; n < 8; n++)
            #pragma unroll
            for (int i = 0; i < 4; i++) o[m][n][i] = 0.0f;
    float mr[2][2], lr[2][2];
    #pragma unroll
    for (int m = 0; m < 2; m++) {
        mr[m][0] = mr[m][1] = -1e30f;
        lr[m][0] = lr[m][1] = 0.0f;
    }

    #pragma unroll 1
    for (int t = 0; t < NT; t++) {
        const int t0 = split * KEYS_PER_SPLIT + t * KTILE;
        __syncthreads();

        // ---- stage K (hi/lo split, 256 tasks) ----
        #pragma unroll
        for (int p = 0; p < 2; p++) {
            const int task = p * 128 + tid;
            const int key  = task >> 3;
            const int c    = task & 7;
            const float* kr = &kb[(long)(t0 + key) * HDIM + c * 8];
            float4 fa = *reinterpret_cast<const float4*>(kr);
            float4 fb = *reinterpret_cast<const float4*>(kr + 4);
            float a_[4] = {fa.x, fa.y, fa.z, fa.w};
            float b_[4] = {fb.x, fb.y, fb.z, fb.w};
            float4* dst = &KP4[key * KSTR4 + c * 4];
            #pragma unroll
            for (int q = 0; q < 4; q++) {
                float ha = tf32_hi(a_[q]);
                float hb = tf32_hi(b_[q]);
                dst[q] = make_float4(ha, hb, a_[q] - ha, b_[q] - hb);
            }
        }
        // ---- stage V^T (hi only, 256 tasks) ----
        #pragma unroll
        for (int p = 0; p < 2; p++) {
            const int task = p * 128 + tid;
            const int bk   = task >> 4;            // 0..15
            const int h4   = (task & 15) * 4;
            const int kk   = bk >> 2;              // 0..3 key-block
            const int tt   = bk & 3;
            const int keyA = kk * 8 + tt;
            const float* va_ = &vb[(long)(t0 + keyA) * HDIM + h4];
            const float* vb_ = &vb[(long)(t0 + keyA + 4) * HDIM + h4];
            float4 fa = *reinterpret_cast<const float4*>(va_);
            float4 fb = *reinterpret_cast<const float4*>(vb_);
            float a_[4] = {fa.x, fa.y, fa.z, fa.w};
            float b_[4] = {fb.x, fb.y, fb.z, fb.w};
            #pragma unroll
            for (int q = 0; q < 4; q++) {
                VP2[(h4 + q) * VSTR2 + kk * 4 + tt] =
                    make_float2(tf32_hi(a_[q]), tf32_hi(b_[q]));
            }
        }
        __syncthreads();

        // ---- QK: S = Q K^T (3xTF32), B shared by both m-tiles ----
        float s[2][4][4];
        #pragma unroll
        for (int m = 0; m < 2; m++)
            #pragma unroll
            for (int n = 0; n < 4; n++)
                #pragma unroll
                for (int i = 0; i < 4; i++) s[m][n][i] = 0.0f;

        #pragma unroll
        for (int k = 0; k < 8; k++) {
            float qh[2][4], ql[2][4];
            #pragma unroll
            for (int m = 0; m < 2; m++) {
                float4 qa = QA[(w * 2 + m) * 256 + k * 32 + tg * 8 + g];
                float v_[4] = {qa.x, qa.y, qa.z, qa.w};
                #pragma unroll
                for (int q = 0; q < 4; q++) {
                    qh[m][q] = tf32_hi(v_[q]);
                    ql[m][q] = v_[q] - qh[m][q];
                }
            }
            const float4* kbase = &KP4[g * KSTR4 + k * 4 + tg];
            #pragma unroll
            for (int n = 0; n < 4; n++) {
                float4 kp = kbase[n * 8 * KSTR4];
                #pragma unroll
                for (int m = 0; m < 2; m++) {
                    mma_tf32(s[m][n][0], s[m][n][1], s[m][n][2], s[m][n][3],
                             qh[m][0], qh[m][1], qh[m][2], qh[m][3], kp.x, kp.y);
                    mma_tf32(s[m][n][0], s[m][n][1], s[m][n][2], s[m][n][3],
                             ql[m][0], ql[m][1], ql[m][2], ql[m][3], kp.x, kp.y);
                    mma_tf32(s[m][n][0], s[m][n][1], s[m][n][2], s[m][n][3],
                             qh[m][0], qh[m][1], qh[m][2], qh[m][3], kp.z, kp.w);
                }
            }
        }

        // ---- online softmax (per m-tile, rows g / g+8) ----
        #pragma unroll
        for (int m = 0; m < 2; m++) {
            const int mb = w * 2 + m;
            float mxA = -1e30f, mxB = -1e30f;
            #pragma unroll
            for (int n = 0; n < 4; n++) {
                mxA = fmaxf(mxA, fmaxf(s[m][n][0], s[m][n][1]));
                mxB = fmaxf(mxB, fmaxf(s[m][n][2], s[m][n][3]));
            }
            mxA = fmaxf(mxA, __shfl_xor_sync(0xffffffffu, mxA, 1));
            mxA = fmaxf(mxA, __shfl_xor_sync(0xffffffffu, mxA, 2));
            mxB = fmaxf(mxB, __shfl_xor_sync(0xffffffffu, mxB, 1));
            mxB = fmaxf(mxB, __shfl_xor_sync(0xffffffffu, mxB, 2));

            const float nmA = fmaxf(mr[m][0], mxA);
            const float nmB = fmaxf(mr[m][1], mxB);
            const float alA = __expf(mr[m][0] - nmA);
            const float alB = __expf(mr[m][1] - nmB);
            mr[m][0] = nmA; mr[m][1] = nmB;

            float lsA = 0.0f, lsB = 0.0f;
            #pragma unroll
            for (int n = 0; n < 4; n++) {
                float p0 = __expf(s[m][n][0] - nmA);
                float p1 = __expf(s[m][n][1] - nmA);
                float p2 = __expf(s[m][n][2] - nmB);
                float p3 = __expf(s[m][n][3] - nmB);
                lsA += p0 + p1;
                lsB += p2 + p3;
                const int c = n * 8 + 2 * tg;
                P2[mb * 256 + c * 8 + g]       = make_float2(p0, p2);
                P2[mb * 256 + (c + 1) * 8 + g] = make_float2(p1, p3);
            }
            lsA += __shfl_xor_sync(0xffffffffu, lsA, 1);
            lsA += __shfl_xor_sync(0xffffffffu, lsA, 2);
            lsB += __shfl_xor_sync(0xffffffffu, lsB, 1);
            lsB += __shfl_xor_sync(0xffffffffu, lsB, 2);
            lr[m][0] = lr[m][0] * alA + lsA;
            lr[m][1] = lr[m][1] * alB + lsB;

            #pragma unroll
            for (int n = 0; n < 8; n++) {
                o[m][n][0] *= alA; o[m][n][1] *= alA;
                o[m][n][2] *= alB; o[m][n][3] *= alB;
            }
        }
        __syncwarp();

        // ---- PV: O += P V (1xTF32), V shared by both m-tiles ----
        #pragma unroll
        for (int k = 0; k < 4; k++) {
            float ah[2][4];
            #pragma unroll
            for (int m = 0; m < 2; m++) {
                const int mb = w * 2 + m;
                float2 pA = P2[mb * 256 + (k * 8 + tg) * 8 + g];
                float2 pB = P2[mb * 256 + (k * 8 + tg + 4) * 8 + g];
                ah[m][0] = tf32_hi(pA.x);
                ah[m][1] = tf32_hi(pA.y);
                ah[m][2] = tf32_hi(pB.x);
                ah[m][3] = tf32_hi(pB.y);
            }
            const float2* vbase = &VP2[g * VSTR2 + k * 4 + tg];
            #pragma unroll
            for (int n = 0; n < 8; n++) {
                float2 vp = vbase[n * 8 * VSTR2];
                #pragma unroll
                for (int m = 0; m < 2; m++) {
                    mma_tf32(o[m][n][0], o[m][n][1], o[m][n][2], o[m][n][3],
                             ah[m][0], ah[m][1], ah[m][2], ah[m][3], vp.x, vp.y);
                }
            }
        }
    }

    // ---- epilogue: write unnormalized partials + (m, l) ----
    #pragma unroll
    for (int m = 0; m < 2; m++) {
        const long rowA = (long)b * TSEQ + q0 + w * 32 + m * 16 + g;
        const long rowB = rowA + 8;
        #pragma unroll
        for (int n = 0; n < 8; n++) {
            const int c = n * 8 + 2 * tg;
            *reinterpret_cast<float2*>(&g_pacc[split][rowA][c]) =
                make_float2(o[m][n][0], o[m][n][1]);
            *reinterpret_cast<float2*>(&g_pacc[split][rowB][c]) =
                make_float2(o[m][n][2], o[m][n][3]);
        }
        if (tg == 0) {
            g_pm[split][rowA] = mr[m][0];
            g_pl[split][rowA] = lr[m][0];
            g_pm[split][rowB] = mr[m][1];
            g_pl[split][rowB] = lr[m][1];
        }
    }
}

// ---------------------------------------------------------------------------
// Combine split-KV partials.
// ---------------------------------------------------------------------------
__global__ __launch_bounds__(128) void combine_kernel(float* __restrict__ out)
{
    const long row = (long)blockIdx.x * 128 + threadIdx.x;

    float m[NSPLIT], w[NSPLIT];
    float M = -1e30f;
    #pragma unroll
    for (int i = 0; i < NSPLIT; i++) {
        m[i] = g_pm[i][row];
        M = fmaxf(M, m[i]);
    }
    float L = 0.0f;
    #pragma unroll
    for (int i = 0; i < NSPLIT; i++) {
        w[i] = __expf(m[i] - M);
        L += w[i] * g_pl[i][row];
    }
    const float inv = 1.0f / L;

    float* __restrict__ orow = &out[row * HDIM];
    #pragma unroll
    for (int h = 0; h < HDIM; h += 4) {
        float4 a = make_float4(0.f, 0.f, 0.f, 0.f);
        #pragma unroll
        for (int i = 0; i < NSPLIT; i++) {
            float4 p = *reinterpret_cast<const float4*>(&g_pacc[i][row][h]);
            a.x += w[i] * p.x;
            a.y += w[i] * p.y;
            a.z += w[i] * p.z;
            a.w += w[i] * p.w;
        }
        a.x *= inv; a.y *= inv; a.z *= inv; a.w *= inv;
        *reinterpret_cast<float4*>(&orow[h]) = a;
    }
}

// ---------------------------------------------------------------------------
extern "C" void kernel_launch(void* const* d_in, const int* in_sizes, int n_in,
                              void* d_out, int out_size)
{
    const float* x  = (const float*)d_in[0];
    const float* Wq = (const float*)d_in[1];
    const float* Wk = (const float*)d_in[2];
    const float* Wv = (const float*)d_in[3];
    float* out = (float*)d_out;

    dim3 pg(BT_TOTAL / 128, 3);
    proj_kernel<<<pg, 256>>>(x, Wq, Wk, Wv);

    const int smem_bytes = 4864 * 16;   // 77,824 B
    static bool attr_set = false;
    if (!attr_set) {
        cudaFuncSetAttribute(attn_mma_kernel,
                             cudaFuncAttributeMaxDynamicSharedMemorySize, smem_bytes);
        attr_set = true;
    }
    dim3 ag(TSEQ / QTILE, BATCH, NSPLIT);
    attn_mma_kernel<<<ag, 128, smem_bytes>>>();

    combine_kernel<<<BT_TOTAL / 128, 128>>>(out);
}

// round 11
// speedup vs baseline: 2.1644x; 1.0679x over previous
#include <cuda_runtime.h>
#include <cstdint>

#define BATCH   4
#define TSEQ    4096
#define CDIM    512
#define HDIM    64
#define BT_TOTAL (BATCH * TSEQ)   // 16384
#define QTILE   128
#define KTILE   32
#define NSPLIT  2
#define KEYS_PER_SPLIT (TSEQ / NSPLIT)     // 2048
#define NT      (KEYS_PER_SPLIT / KTILE)   // 64

#define KSTR4   36   // K row stride (float4): 32 entries used
#define VSTR2   20   // V^T row stride (float2): 16 entries used
#define WSTR4   20   // W row stride (float4): 16 entries used
#define XSTR    36   // xs row stride (floats): conflict-free A-frag LDS.32

typedef unsigned long long u64;

// ---- tf32 helpers ----
__device__ __forceinline__ float tf32_hi(float a) {
    unsigned u;
    asm("cvt.rna.tf32.f32 %0, %1;" : "=r"(u) : "f"(a));
    return __uint_as_float(u);
}
__device__ __forceinline__ void mma_tf32(
    float& c0, float& c1, float& c2, float& c3,
    float a0, float a1, float a2, float a3,
    float b0, float b1)
{
    unsigned A0 = __float_as_uint(a0), A1 = __float_as_uint(a1);
    unsigned A2 = __float_as_uint(a2), A3 = __float_as_uint(a3);
    unsigned B0 = __float_as_uint(b0), B1 = __float_as_uint(b1);
    asm("mma.sync.aligned.m16n8k8.row.col.f32.tf32.tf32.f32 "
        "{%0,%1,%2,%3},{%4,%5,%6,%7},{%8,%9},{%0,%1,%2,%3};"
        : "+f"(c0), "+f"(c1), "+f"(c2), "+f"(c3)
        : "r"(A0), "r"(A1), "r"(A2), "r"(A3), "r"(B0), "r"(B1));
}

// Scratch (static device arrays per allocation rules).
__device__ float g_q[BT_TOTAL * HDIM];
__device__ float g_k[BT_TOTAL * HDIM];
__device__ float g_v[BT_TOTAL * HDIM];
__device__ float g_wt[3][HDIM][CDIM];      // transposed weights [mat][n][k]
// split-KV partials
__device__ float g_pacc[NSPLIT][BT_TOTAL][HDIM];
__device__ float g_pm[NSPLIT][BT_TOTAL];
__device__ float g_pl[NSPLIT][BT_TOTAL];

// ---------------------------------------------------------------------------
// Transpose W [512][64] -> g_wt [64][512].  grid (128, 3), block 256.
// ---------------------------------------------------------------------------
__global__ __launch_bounds__(256) void transpose_w_kernel(
    const float* __restrict__ Wq,
    const float* __restrict__ Wk,
    const float* __restrict__ Wv)
{
    const int mat = blockIdx.y;
    const float* __restrict__ W = (mat == 0) ? Wq : (mat == 1) ? Wk : Wv;
    const int idx = blockIdx.x * 256 + threadIdx.x;   // 0..32767
    const int k = idx & (CDIM - 1);
    const int n = idx >> 9;
    g_wt[mat][n][k] = W[k * HDIM + n];
}

// ---------------------------------------------------------------------------
// Tensor-core projection GEMM, 3xTF32.
// out[16384,64] = x[16384,512] @ W[512,64], x3. Q scaled by 8.
// grid (BT/128, 3), block 128 (4 warps x m32 rows).
// ---------------------------------------------------------------------------
__global__ __launch_bounds__(128) void proj_mma_kernel(const float* __restrict__ x)
{
    __shared__ float  xs[128 * XSTR];          // raw x tile [128][32], pad 36
    __shared__ float4 Wsm[HDIM * WSTR4];       // packed {hiA,hiB,loA,loB} W frags

    const int mat  = blockIdx.y;
    float* __restrict__ out = (mat == 0) ? g_q : (mat == 1) ? g_k : g_v;
    const int row0 = blockIdx.x * 128;
    const int tid  = threadIdx.x;
    const int w    = tid >> 5;
    const int ln   = tid & 31;
    const int g    = ln >> 2;
    const int tg   = ln & 3;

    float o[2][8][4];
    #pragma unroll
    for (int m = 0; m < 2; m++)
        #pragma unroll
        for (int n = 0; n < 8; n++)
            #pragma unroll
            for (int i = 0; i < 4; i++) o[m][n][i] = 0.0f;

    #pragma unroll 1
    for (int k0 = 0; k0 < CDIM; k0 += 32) {
        __syncthreads();
        // ---- stage x raw: 1024 tasks (128 rows x 8 col-grps), 8 per thread ----
        #pragma unroll
        for (int p = 0; p < 8; p++) {
            const int task = p * 128 + tid;
            const int r    = task >> 3;
            const int cg   = task & 7;
            float4 v = *reinterpret_cast<const float4*>(
                &x[(long)(row0 + r) * CDIM + k0 + cg * 4]);
            *reinterpret_cast<float4*>(&xs[r * XSTR + cg * 4]) = v;
        }
        // ---- stage W (hi/lo packed B-frags): 256 tasks (64 n x 4 kblocks) ----
        #pragma unroll
        for (int p = 0; p < 2; p++) {
            const int task = p * 128 + tid;
            const int n    = task >> 2;
            const int c    = task & 3;
            const float* wr = &g_wt[mat][n][k0 + c * 8];
            float4 fa = *reinterpret_cast<const float4*>(wr);
            float4 fb = *reinterpret_cast<const float4*>(wr + 4);
            float a_[4] = {fa.x, fa.y, fa.z, fa.w};
            float b_[4] = {fb.x, fb.y, fb.z, fb.w};
            float4* dst = &Wsm[n * WSTR4 + c * 4];
            #pragma unroll
            for (int q = 0; q < 4; q++) {
                float ha = tf32_hi(a_[q]);
                float hb = tf32_hi(b_[q]);
                dst[q] = make_float4(ha, hb, a_[q] - ha, b_[q] - hb);
            }
        }
        __syncthreads();

        // ---- mma mainloop: 4 kblocks x 8 n-tiles x 2 m x 3 products ----
        #pragma unroll
        for (int kb = 0; kb < 4; kb++) {
            float ah[2][4], al[2][4];
            #pragma unroll
            for (int m = 0; m < 2; m++) {
                const int r = w * 32 + m * 16 + g;
                float a0 = xs[r * XSTR + kb * 8 + tg];
                float a1 = xs[(r + 8) * XSTR + kb * 8 + tg];
                float a2 = xs[r * XSTR + kb * 8 + tg + 4];
                float a3 = xs[(r + 8) * XSTR + kb * 8 + tg + 4];
                ah[m][0] = tf32_hi(a0); al[m][0] = a0 - ah[m][0];
                ah[m][1] = tf32_hi(a1); al[m][1] = a1 - ah[m][1];
                ah[m][2] = tf32_hi(a2); al[m][2] = a2 - ah[m][2];
                ah[m][3] = tf32_hi(a3); al[m][3] = a3 - ah[m][3];
            }
            #pragma unroll
            for (int n = 0; n < 8; n++) {
                float4 wp = Wsm[(n * 8 + g) * WSTR4 + kb * 4 + tg];
                #pragma unroll
                for (int m = 0; m < 2; m++) {
                    mma_tf32(o[m][n][0], o[m][n][1], o[m][n][2], o[m][n][3],
                             ah[m][0], ah[m][1], ah[m][2], ah[m][3], wp.x, wp.y);
                    mma_tf32(o[m][n][0], o[m][n][1], o[m][n][2], o[m][n][3],
                             al[m][0], al[m][1], al[m][2], al[m][3], wp.x, wp.y);
                    mma_tf32(o[m][n][0], o[m][n][1], o[m][n][2], o[m][n][3],
                             ah[m][0], ah[m][1], ah[m][2], ah[m][3], wp.z, wp.w);
                }
            }
        }
    }

    // ---- epilogue ----
    const float scale = (mat == 0) ? 8.0f : 1.0f;
    #pragma unroll
    for (int m = 0; m < 2; m++) {
        const long rowA = (long)(row0 + w * 32 + m * 16 + g);
        const long rowB = rowA + 8;
        #pragma unroll
        for (int n = 0; n < 8; n++) {
            const int c = n * 8 + 2 * tg;
            *reinterpret_cast<float2*>(&out[rowA * HDIM + c]) =
                make_float2(o[m][n][0] * scale, o[m][n][1] * scale);
            *reinterpret_cast<float2*>(&out[rowB * HDIM + c]) =
                make_float2(o[m][n][2] * scale, o[m][n][3] * scale);
        }
    }
}

// ---------------------------------------------------------------------------
// mma.sync flash attention. QK = 3xTF32, PV = 1xTF32.
// K/V global loads double-buffered through registers (prefetch t+1 during
// compute of t). grid (TSEQ/QTILE, BATCH, NSPLIT), block 128.
// ---------------------------------------------------------------------------
__global__ __launch_bounds__(128) void attn_mma_kernel()
{
    extern __shared__ float4 sm4[];
    float4* KP4 = sm4;                                     // 1152 f4
    float2* VP2 = reinterpret_cast<float2*>(sm4 + 1152);   // 1280 f2
    float4* QA  = sm4 + 1792;                              // 2048 f4
    float2* P2  = reinterpret_cast<float2*>(sm4 + 3840);   // 2048 f2

    const int b     = blockIdx.y;
    const int split = blockIdx.z;
    const int q0    = blockIdx.x * QTILE;
    const int tid   = threadIdx.x;
    const int w     = tid >> 5;
    const int ln    = tid & 31;
    const int g     = ln >> 2;
    const int tg    = ln & 3;

    const float* __restrict__ kb = &g_k[(long)b * TSEQ * HDIM];
    const float* __restrict__ vb = &g_v[(long)b * TSEQ * HDIM];

    // K staging indices (per p-task)
    const int kkey0 = tid >> 3;          // p=0: key
    const int kc0   = tid & 7;
    const int kkey1 = (128 + tid) >> 3;  // p=1
    const int kc1   = (128 + tid) & 7;
    // V staging indices
    int vkeyA[2], vh4[2], vkk[2], vtt[2];
    #pragma unroll
    for (int p = 0; p < 2; p++) {
        const int task = p * 128 + tid;
        const int bk   = task >> 4;
        vh4[p] = (task & 15) * 4;
        vkk[p] = bk >> 2;
        vtt[p] = bk & 3;
        vkeyA[p] = vkk[p] * 8 + vtt[p];
    }

    // ---- stage Q (raw, A-fragment packed) ----
    #pragma unroll
    for (int i = 0; i < 16; i++) {
        const int e  = tid * 16 + i;
        const int mb = e >> 8;
        const int k  = (e >> 5) & 7;
        const int t2 = (e >> 3) & 3;
        const int g2 = e & 7;
        const int r  = (mb >> 1) * 32 + (mb & 1) * 16 + g2;
        const int c  = k * 8 + t2;
        const float* q0p = &g_q[((long)b * TSEQ + q0 + r) * HDIM];
        const float* q1p = &g_q[((long)b * TSEQ + q0 + r + 8) * HDIM];
        QA[e] = make_float4(q0p[c], q1p[c], q0p[c + 4], q1p[c + 4]);
    }

    float o[2][8][4];
    #pragma unroll
    for (int m = 0; m < 2; m++)
        #pragma unroll
        for (int n = 0; n < 8; n++)
            #pragma unroll
            for (int i = 0; i < 4; i++) o[m][n][i] = 0.0f;
    float mr[2][2], lr[2][2];
    #pragma unroll
    for (int m = 0; m < 2; m++) {
        mr[m][0] = mr[m][1] = -1e30f;
        lr[m][0] = lr[m][1] = 0.0f;
    }

    // ---- prologue: prefetch tile 0 into registers ----
    float4 kfa[2], kfb[2], vfa[2], vfb[2];
    {
        const int t0 = split * KEYS_PER_SPLIT;
        kfa[0] = *reinterpret_cast<const float4*>(&kb[(long)(t0 + kkey0) * HDIM + kc0 * 8]);
        kfb[0] = *reinterpret_cast<const float4*>(&kb[(long)(t0 + kkey0) * HDIM + kc0 * 8 + 4]);
        kfa[1] = *reinterpret_cast<const float4*>(&kb[(long)(t0 + kkey1) * HDIM + kc1 * 8]);
        kfb[1] = *reinterpret_cast<const float4*>(&kb[(long)(t0 + kkey1) * HDIM + kc1 * 8 + 4]);
        #pragma unroll
        for (int p = 0; p < 2; p++) {
            vfa[p] = *reinterpret_cast<const float4*>(&vb[(long)(t0 + vkeyA[p]) * HDIM + vh4[p]]);
            vfb[p] = *reinterpret_cast<const float4*>(&vb[(long)(t0 + vkeyA[p] + 4) * HDIM + vh4[p]]);
        }
    }

    #pragma unroll 1
    for (int t = 0; t < NT; t++) {
        __syncthreads();
        // ---- write staged K from regs (hi/lo split) ----
        #pragma unroll
        for (int p = 0; p < 2; p++) {
            const int key = p ? kkey1 : kkey0;
            const int c   = p ? kc1 : kc0;
            float4 fa = kfa[p], fb = kfb[p];
            float a_[4] = {fa.x, fa.y, fa.z, fa.w};
            float b_[4] = {fb.x, fb.y, fb.z, fb.w};
            float4* dst = &KP4[key * KSTR4 + c * 4];
            #pragma unroll
            for (int q = 0; q < 4; q++) {
                float ha = tf32_hi(a_[q]);
                float hb = tf32_hi(b_[q]);
                dst[q] = make_float4(ha, hb, a_[q] - ha, b_[q] - hb);
            }
        }
        // ---- write staged V^T from regs (hi only) ----
        #pragma unroll
        for (int p = 0; p < 2; p++) {
            float4 fa = vfa[p], fb = vfb[p];
            float a_[4] = {fa.x, fa.y, fa.z, fa.w};
            float b_[4] = {fb.x, fb.y, fb.z, fb.w};
            #pragma unroll
            for (int q = 0; q < 4; q++) {
                VP2[(vh4[p] + q) * VSTR2 + vkk[p] * 4 + vtt[p]] =
                    make_float2(tf32_hi(a_[q]), tf32_hi(b_[q]));
            }
        }
        __syncthreads();

        // ---- prefetch tile t+1 (latency hidden behind compute) ----
        if (t + 1 < NT) {
            const int tn_ = split * KEYS_PER_SPLIT + (t + 1) * KTILE;
            kfa[0] = *reinterpret_cast<const float4*>(&kb[(long)(tn_ + kkey0) * HDIM + kc0 * 8]);
            kfb[0] = *reinterpret_cast<const float4*>(&kb[(long)(tn_ + kkey0) * HDIM + kc0 * 8 + 4]);
            kfa[1] = *reinterpret_cast<const float4*>(&kb[(long)(tn_ + kkey1) * HDIM + kc1 * 8]);
            kfb[1] = *reinterpret_cast<const float4*>(&kb[(long)(tn_ + kkey1) * HDIM + kc1 * 8 + 4]);
            #pragma unroll
            for (int p = 0; p < 2; p++) {
                vfa[p] = *reinterpret_cast<const float4*>(&vb[(long)(tn_ + vkeyA[p]) * HDIM + vh4[p]]);
                vfb[p] = *reinterpret_cast<const float4*>(&vb[(long)(tn_ + vkeyA[p] + 4) * HDIM + vh4[p]]);
            }
        }

        // ---- QK: S = Q K^T (3xTF32) ----
        float s[2][4][4];
        #pragma unroll
        for (int m = 0; m < 2; m++)
            #pragma unroll
            for (int n = 0; n < 4; n++)
                #pragma unroll
                for (int i = 0; i < 4; i++) s[m][n][i] = 0.0f;

        #pragma unroll
        for (int k = 0; k < 8; k++) {
            float qh[2][4], ql[2][4];
            #pragma unroll
            for (int m = 0; m < 2; m++) {
                float4 qa = QA[(w * 2 + m) * 256 + k * 32 + tg * 8 + g];
                float v_[4] = {qa.x, qa.y, qa.z, qa.w};
                #pragma unroll
                for (int q = 0; q < 4; q++) {
                    qh[m][q] = tf32_hi(v_[q]);
                    ql[m][q] = v_[q] - qh[m][q];
                }
            }
            const float4* kbase = &KP4[g * KSTR4 + k * 4 + tg];
            #pragma unroll
            for (int n = 0; n < 4; n++) {
                float4 kp = kbase[n * 8 * KSTR4];
                #pragma unroll
                for (int m = 0; m < 2; m++) {
                    mma_tf32(s[m][n][0], s[m][n][1], s[m][n][2], s[m][n][3],
                             qh[m][0], qh[m][1], qh[m][2], qh[m][3], kp.x, kp.y);
                    mma_tf32(s[m][n][0], s[m][n][1], s[m][n][2], s[m][n][3],
                             ql[m][0], ql[m][1], ql[m][2], ql[m][3], kp.x, kp.y);
                    mma_tf32(s[m][n][0], s[m][n][1], s[m][n][2], s[m][n][3],
                             qh[m][0], qh[m][1], qh[m][2], qh[m][3], kp.z, kp.w);
                }
            }
        }

        // ---- online softmax ----
        #pragma unroll
        for (int m = 0; m < 2; m++) {
            const int mb = w * 2 + m;
            float mxA = -1e30f, mxB = -1e30f;
            #pragma unroll
            for (int n = 0; n < 4; n++) {
                mxA = fmaxf(mxA, fmaxf(s[m][n][0], s[m][n][1]));
                mxB = fmaxf(mxB, fmaxf(s[m][n][2], s[m][n][3]));
            }
            mxA = fmaxf(mxA, __shfl_xor_sync(0xffffffffu, mxA, 1));
            mxA = fmaxf(mxA, __shfl_xor_sync(0xffffffffu, mxA, 2));
            mxB = fmaxf(mxB, __shfl_xor_sync(0xffffffffu, mxB, 1));
            mxB = fmaxf(mxB, __shfl_xor_sync(0xffffffffu, mxB, 2));

            const float nmA = fmaxf(mr[m][0], mxA);
            const float nmB = fmaxf(mr[m][1], mxB);
            const float alA = __expf(mr[m][0] - nmA);
            const float alB = __expf(mr[m][1] - nmB);
            mr[m][0] = nmA; mr[m][1] = nmB;

            float lsA = 0.0f, lsB = 0.0f;
            #pragma unroll
            for (int n = 0; n < 4; n++) {
                float p0 = __expf(s[m][n][0] - nmA);
                float p1 = __expf(s[m][n][1] - nmA);
                float p2 = __expf(s[m][n][2] - nmB);
                float p3 = __expf(s[m][n][3] - nmB);
                lsA += p0 + p1;
                lsB += p2 + p3;
                const int c = n * 8 + 2 * tg;
                P2[mb * 256 + c * 8 + g]       = make_float2(p0, p2);
                P2[mb * 256 + (c + 1) * 8 + g] = make_float2(p1, p3);
            }
            lsA += __shfl_xor_sync(0xffffffffu, lsA, 1);
            lsA += __shfl_xor_sync(0xffffffffu, lsA, 2);
            lsB += __shfl_xor_sync(0xffffffffu, lsB, 1);
            lsB += __shfl_xor_sync(0xffffffffu, lsB, 2);
            lr[m][0] = lr[m][0] * alA + lsA;
            lr[m][1] = lr[m][1] * alB + lsB;

            #pragma unroll
            for (int n = 0; n < 8; n++) {
                o[m][n][0] *= alA; o[m][n][1] *= alA;
                o[m][n][2] *= alB; o[m][n][3] *= alB;
            }
        }
        __syncwarp();

        // ---- PV: O += P V (1xTF32) ----
        #pragma unroll
        for (int k = 0; k < 4; k++) {
            float ah[2][4];
            #pragma unroll
            for (int m = 0; m < 2; m++) {
                const int mb = w * 2 + m;
                float2 pA = P2[mb * 256 + (k * 8 + tg) * 8 + g];
                float2 pB = P2[mb * 256 + (k * 8 + tg + 4) * 8 + g];
                ah[m][0] = tf32_hi(pA.x);
                ah[m][1] = tf32_hi(pA.y);
                ah[m][2] = tf32_hi(pB.x);
                ah[m][3] = tf32_hi(pB.y);
            }
            const float2* vbase = &VP2[g * VSTR2 + k * 4 + tg];
            #pragma unroll
            for (int n = 0; n < 8; n++) {
                float2 vp = vbase[n * 8 * VSTR2];
                #pragma unroll
                for (int m = 0; m < 2; m++) {
                    mma_tf32(o[m][n][0], o[m][n][1], o[m][n][2], o[m][n][3],
                             ah[m][0], ah[m][1], ah[m][2], ah[m][3], vp.x, vp.y);
                }
            }
        }
    }

    // ---- epilogue: write unnormalized partials + (m, l) ----
    #pragma unroll
    for (int m = 0; m < 2; m++) {
        const long rowA = (long)b * TSEQ + q0 + w * 32 + m * 16 + g;
        const long rowB = rowA + 8;
        #pragma unroll
        for (int n = 0; n < 8; n++) {
            const int c = n * 8 + 2 * tg;
            *reinterpret_cast<float2*>(&g_pacc[split][rowA][c]) =
                make_float2(o[m][n][0], o[m][n][1]);
            *reinterpret_cast<float2*>(&g_pacc[split][rowB][c]) =
                make_float2(o[m][n][2], o[m][n][3]);
        }
        if (tg == 0) {
            g_pm[split][rowA] = mr[m][0];
            g_pl[split][rowA] = lr[m][0];
            g_pm[split][rowB] = mr[m][1];
            g_pl[split][rowB] = lr[m][1];
        }
    }
}

// ---------------------------------------------------------------------------
// Combine split-KV partials.
// ---------------------------------------------------------------------------
__global__ __launch_bounds__(128) void combine_kernel(float* __restrict__ out)
{
    const long row = (long)blockIdx.x * 128 + threadIdx.x;

    float m[NSPLIT], w[NSPLIT];
    float M = -1e30f;
    #pragma unroll
    for (int i = 0; i < NSPLIT; i++) {
        m[i] = g_pm[i][row];
        M = fmaxf(M, m[i]);
    }
    float L = 0.0f;
    #pragma unroll
    for (int i = 0; i < NSPLIT; i++) {
        w[i] = __expf(m[i] - M);
        L += w[i] * g_pl[i][row];
    }
    const float inv = 1.0f / L;

    float* __restrict__ orow = &out[row * HDIM];
    #pragma unroll
    for (int h = 0; h < HDIM; h += 4) {
        float4 a = make_float4(0.f, 0.f, 0.f, 0.f);
        #pragma unroll
        for (int i = 0; i < NSPLIT; i++) {
            float4 p = *reinterpret_cast<const float4*>(&g_pacc[i][row][h]);
            a.x += w[i] * p.x;
            a.y += w[i] * p.y;
            a.z += w[i] * p.z;
            a.w += w[i] * p.w;
        }
        a.x *= inv; a.y *= inv; a.z *= inv; a.w *= inv;
        *reinterpret_cast<float4*>(&orow[h]) = a;
    }
}

// ---------------------------------------------------------------------------
extern "C" void kernel_launch(void* const* d_in, const int* in_sizes, int n_in,
                              void* d_out, int out_size)
{
    const float* x  = (const float*)d_in[0];
    const float* Wq = (const float*)d_in[1];
    const float* Wk = (const float*)d_in[2];
    const float* Wv = (const float*)d_in[3];
    float* out = (float*)d_out;

    transpose_w_kernel<<<dim3(128, 3), 256>>>(Wq, Wk, Wv);

    proj_mma_kernel<<<dim3(BT_TOTAL / 128, 3), 128>>>(x);

    const int smem_bytes = 4864 * 16;   // 77,824 B
    static bool attr_set = false;
    if (!attr_set) {
        cudaFuncSetAttribute(attn_mma_kernel,
                             cudaFuncAttributeMaxDynamicSharedMemorySize, smem_bytes);
        attr_set = true;
    }
    dim3 ag(TSEQ / QTILE, BATCH, NSPLIT);
    attn_mma_kernel<<<ag, 128, smem_bytes>>>();

    combine_kernel<<<BT_TOTAL / 128, 128>>>(out);
}